// round 14
// baseline (speedup 1.0000x reference)
#include <cuda_runtime.h>
#include <cuda_bf16.h>
#include <cstdint>
#include <math.h>

#define NBATCH 16
#define NNODE  1024
#define HD     256
#define NROWS  (NBATCH*NNODE)
#define TOTEL  16777216

__device__ float d_hid[NROWS*768];
__device__ float d_hs [NROWS*HD];
__device__ float d_g  [NROWS*HD];
__device__ float d_u1 [NROWS*HD];
__device__ float d_u2 [NROWS*HD];
__device__ float d_u3 [NROWS*HD];
__device__ float d_u4 [NROWS*HD];
__device__ float d_hp [NROWS*HD];
__device__ float d_mid[NROWS*HD];
__device__ float d_logits[TOTEL];
__device__ float d_dis[NROWS];
__device__ float d_invdeg[NROWS];
__device__ float d_Rv[NROWS];
__device__ float d_Cv[NROWS];
__device__ float d_Tv[NROWS];

__device__ __forceinline__ float leakyf(float x){ return x > 0.f ? x : 0.01f*x; }

__global__ void k_adj_stats(const float* __restrict__ adj){
    int row  = blockIdx.x*8 + (threadIdx.x>>5);
    int lane = threadIdx.x & 31;
    const float* a = adj + (size_t)row*NNODE;
    float s = 0.f;
    #pragma unroll
    for (int k=0;k<32;k++) s += a[lane + 32*k];
    #pragma unroll
    for (int o=16;o;o>>=1) s += __shfl_xor_sync(0xffffffffu, s, o);
    if (lane==0){ d_dis[row] = rsqrtf(s + 1.f); d_invdeg[row] = 1.f/s; }
}

__global__ void k_scale_hs(int off){
    int idx = blockIdx.x*256 + threadIdx.x;
    int row = idx >> 8, col = idx & 255;
    d_hs[idx] = d_dis[row] * d_hid[(size_t)row*768 + off + col];
}

// ---------------- 3xTF32 mma.sync helpers ----------------
__device__ __forceinline__ float2 split2(float v){
    uint32_t h;
    asm("cvt.rna.tf32.f32 %0, %1;" : "=r"(h) : "f"(v));
    float hf = __uint_as_float(h);
    float r = v - hf;
    uint32_t l;
    asm("cvt.rna.tf32.f32 %0, %1;" : "=r"(l) : "f"(r));
    return make_float2(hf, __uint_as_float(l));
}
__device__ __forceinline__ void mma_tf32(float* c,
    uint32_t a0, uint32_t a1, uint32_t a2, uint32_t a3,
    uint32_t b0, uint32_t b1){
    asm volatile(
        "mma.sync.aligned.m16n8k8.row.col.f32.tf32.tf32.f32 "
        "{%0,%1,%2,%3}, {%4,%5,%6,%7}, {%8,%9}, {%0,%1,%2,%3};"
        : "+f"(c[0]), "+f"(c[1]), "+f"(c[2]), "+f"(c[3])
        : "r"(a0), "r"(a1), "r"(a2), "r"(a3), "r"(b0), "r"(b1));
}
#define U(x) __float_as_uint(x)

#define PAD2 130
#define SM2TOT (4*16*PAD2*8)   /* 2 ops x 2 buffers x 16 x PAD2 float2 = 66560 B */

// ---------------- shared mainloop + epilogue macros ----------------
#define MMA_MAINLOOP(APTR, BPTR, LDB)                                                        \
    float2 (*As2)[16][PAD2] = (float2(*)[16][PAD2])sm2;                                      \
    float2 (*Bs2)[16][PAD2] = (float2(*)[16][PAD2])(sm2 + 2*16*PAD2);                        \
    {                                                                                        \
        float4 a0 = *(const float4*)(APTR);                                                  \
        float4 a1 = *(const float4*)(APTR + 4);                                              \
        float4 b0 = *(const float4*)(BPTR);                                                  \
        float4 b1 = *(const float4*)(BPTR + 4);                                              \
        As2[0][acol+0][arow]=split2(a0.x); As2[0][acol+1][arow]=split2(a0.y);                \
        As2[0][acol+2][arow]=split2(a0.z); As2[0][acol+3][arow]=split2(a0.w);                \
        As2[0][acol+4][arow]=split2(a1.x); As2[0][acol+5][arow]=split2(a1.y);                \
        As2[0][acol+6][arow]=split2(a1.z); As2[0][acol+7][arow]=split2(a1.w);                \
        Bs2[0][brow][bcol+0]=split2(b0.x); Bs2[0][brow][bcol+1]=split2(b0.y);                \
        Bs2[0][brow][bcol+2]=split2(b0.z); Bs2[0][brow][bcol+3]=split2(b0.w);                \
        Bs2[0][brow][bcol+4]=split2(b1.x); Bs2[0][brow][bcol+5]=split2(b1.y);                \
        Bs2[0][brow][bcol+6]=split2(b1.z); Bs2[0][brow][bcol+7]=split2(b1.w);                \
    }                                                                                        \
    __syncthreads();                                                                         \
    const int ntile = NNODE/16;                                                              \
    for (int t = 0; t < ntile; t++){                                                         \
        int cur = t & 1;                                                                     \
        float4 pa0, pa1, pb0, pb1;                                                           \
        if (t+1 < ntile){                                                                    \
            pa0 = *(const float4*)((APTR) + (t+1)*16);                                       \
            pa1 = *(const float4*)((APTR) + (t+1)*16 + 4);                                   \
            pb0 = *(const float4*)((BPTR) + (size_t)(t+1)*16*(LDB));                         \
            pb1 = *(const float4*)((BPTR) + (size_t)(t+1)*16*(LDB) + 4);                     \
        }                                                                                    \
        _Pragma("unroll")                                                                    \
        for (int k8 = 0; k8 < 16; k8 += 8){                                                  \
            float2 Af[2][4];                                                                 \
            _Pragma("unroll")                                                                \
            for (int f = 0; f < 2; f++){                                                     \
                int mb = wm + f*16 + lr;                                                     \
                Af[f][0] = As2[cur][k8+lc][mb];                                              \
                Af[f][1] = As2[cur][k8+lc][mb+8];                                            \
                Af[f][2] = As2[cur][k8+lc+4][mb];                                            \
                Af[f][3] = As2[cur][k8+lc+4][mb+8];                                          \
            }                                                                                \
            _Pragma("unroll")                                                                \
            for (int gh = 0; gh < 2; gh++){                                                  \
                float2 Bf[4][2];                                                             \
                _Pragma("unroll")                                                            \
                for (int g = 0; g < 4; g++){                                                 \
                    int n = wn + gh*32 + g*8 + lr;                                           \
                    Bf[g][0] = Bs2[cur][k8+lc][n];                                           \
                    Bf[g][1] = Bs2[cur][k8+lc+4][n];                                         \
                }                                                                            \
                _Pragma("unroll")                                                            \
                for (int f = 0; f < 2; f++)                                                  \
                _Pragma("unroll")                                                            \
                for (int g = 0; g < 4; g++){                                                 \
                    float* c = acc[f][gh*4+g];                                               \
                    mma_tf32(c, U(Af[f][0].x),U(Af[f][1].x),U(Af[f][2].x),U(Af[f][3].x),     \
                                U(Bf[g][0].x),U(Bf[g][1].x));                                \
                    mma_tf32(c, U(Af[f][0].x),U(Af[f][1].x),U(Af[f][2].x),U(Af[f][3].x),     \
                                U(Bf[g][0].y),U(Bf[g][1].y));                                \
                    mma_tf32(c, U(Af[f][0].y),U(Af[f][1].y),U(Af[f][2].y),U(Af[f][3].y),     \
                                U(Bf[g][0].x),U(Bf[g][1].x));                                \
                }                                                                            \
            }                                                                                \
        }                                                                                    \
        if (t+1 < ntile){                                                                    \
            int nxt = cur ^ 1;                                                               \
            __syncthreads();                                                                 \
            As2[nxt][acol+0][arow]=split2(pa0.x); As2[nxt][acol+1][arow]=split2(pa0.y);      \
            As2[nxt][acol+2][arow]=split2(pa0.z); As2[nxt][acol+3][arow]=split2(pa0.w);      \
            As2[nxt][acol+4][arow]=split2(pa1.x); As2[nxt][acol+5][arow]=split2(pa1.y);      \
            As2[nxt][acol+6][arow]=split2(pa1.z); As2[nxt][acol+7][arow]=split2(pa1.w);      \
            Bs2[nxt][brow][bcol+0]=split2(pb0.x); Bs2[nxt][brow][bcol+1]=split2(pb0.y);      \
            Bs2[nxt][brow][bcol+2]=split2(pb0.z); Bs2[nxt][brow][bcol+3]=split2(pb0.w);      \
            Bs2[nxt][brow][bcol+4]=split2(pb1.x); Bs2[nxt][brow][bcol+5]=split2(pb1.y);      \
            Bs2[nxt][brow][bcol+6]=split2(pb1.z); Bs2[nxt][brow][bcol+7]=split2(pb1.w);      \
            __syncthreads();                                                                 \
        }                                                                                    \
    }

#define MMA_EPILOGUE(MODE, AUX, LDAUX, VEC, OUT)                                             \
    _Pragma("unroll")                                                                        \
    for (int f = 0; f < 2; f++){                                                             \
        int r0 = m0 + wm + f*16 + lr;                                                        \
        size_t gi0 = (size_t)(bb*NNODE + r0);                                                \
        size_t gi1 = gi0 + 8;                                                                \
        float dv0 = (VEC)[gi0], dv1 = (VEC)[gi1];                                            \
        const float* aux0 = (AUX) + gi0*(size_t)(LDAUX) + n0 + wn;                           \
        const float* aux1 = (AUX) + gi1*(size_t)(LDAUX) + n0 + wn;                           \
        float* out0 = (OUT) + gi0*(size_t)256 + n0 + wn;                                     \
        float* out1 = (OUT) + gi1*(size_t)256 + n0 + wn;                                     \
        _Pragma("unroll")                                                                    \
        for (int g = 0; g < 8; g++){                                                         \
            int c = g*8 + lc*2;                                                              \
            float2 ax0 = *(const float2*)(aux0 + c);                                         \
            float2 ax1 = *(const float2*)(aux1 + c);                                         \
            float* a = acc[f][g];                                                            \
            float2 o0, o1;                                                                   \
            if ((MODE) == 1){                                                                \
                o0.x = leakyf(dv0*(a[0]+ax0.x)); o0.y = leakyf(dv0*(a[1]+ax0.y));            \
                o1.x = leakyf(dv1*(a[2]+ax1.x)); o1.y = leakyf(dv1*(a[3]+ax1.y));            \
            } else {                                                                         \
                o0.x = 0.5f*(ax0.x + a[0]*dv0); o0.y = 0.5f*(ax0.y + a[1]*dv0);              \
                o1.x = 0.5f*(ax1.x + a[2]*dv1); o1.y = 0.5f*(ax1.y + a[3]*dv1);              \
            }                                                                                \
            *(float2*)(out0 + c) = o0;                                                       \
            *(float2*)(out1 + c) = o1;                                                       \
        }                                                                                    \
    }

// batched adj GEMM on tensor cores (3xTF32, split-at-store)
__global__ __launch_bounds__(256,2) void k_mma(
    const float* __restrict__ Aadj, const float* __restrict__ B, int ldb,
    float* __restrict__ Cc, int mode,
    const float* __restrict__ aux, int ldaux, const float* __restrict__ vec)
{
    extern __shared__ float2 sm2[];
    int bb = blockIdx.z;
    int n0 = blockIdx.x * 128;
    int m0 = blockIdx.y * 128;
    const float* Ab = Aadj + (size_t)bb*NNODE*NNODE;
    int tid  = threadIdx.x;
    int wid  = tid >> 5, lane = tid & 31;
    int lr = lane >> 2, lc = lane & 3;
    int wm = (wid & 3) * 32;
    int wn = (wid >> 2) * 64;
    int arow = tid >> 1, acol = (tid & 1)*8;
    int brow = tid >> 4, bcol = (tid & 15)*8;

    const float* aptr = Ab + (size_t)(m0+arow)*NNODE + acol;
    const float* bptr = B + (size_t)(bb*NNODE + brow)*ldb + n0 + bcol;
    float acc[2][8][4] = {};
    MMA_MAINLOOP(aptr, bptr, ldb)
    MMA_EPILOGUE(mode, aux, ldaux, vec, Cc)
}

// fused: blockIdx.x 0-1 -> GCN (B1->C1, mode1), 2-3 -> lazy walk (B2->C2, mode2)
__global__ __launch_bounds__(256,2) void k_mma_dual(
    const float* __restrict__ Aadj,
    const float* __restrict__ B1, float* __restrict__ C1, const float* __restrict__ vec1,
    const float* __restrict__ B2, int ldb2, float* __restrict__ C2, const float* __restrict__ vec2)
{
    extern __shared__ float2 sm2[];
    int bb = blockIdx.z;
    int half = blockIdx.x >> 1;
    int n0 = (blockIdx.x & 1) * 128;
    int m0 = blockIdx.y * 128;
    const float* Ab = Aadj + (size_t)bb*NNODE*NNODE;
    int tid  = threadIdx.x;
    int wid  = tid >> 5, lane = tid & 31;
    int lr = lane >> 2, lc = lane & 3;
    int wm = (wid & 3) * 32;
    int wn = (wid >> 2) * 64;
    int arow = tid >> 1, acol = (tid & 1)*8;
    int brow = tid >> 4, bcol = (tid & 15)*8;

    const float* B = half ? B2 : B1;
    int ldb        = half ? ldb2 : 256;
    const float* aptr = Ab + (size_t)(m0+arow)*NNODE + acol;
    const float* bptr = B + (size_t)(bb*NNODE + brow)*ldb + n0 + bcol;
    float acc[2][8][4] = {};
    MMA_MAINLOOP(aptr, bptr, ldb)
    if (half == 0){
        MMA_EPILOGUE(1, B1, 256, vec1, C1)
    } else {
        MMA_EPILOGUE(2, B2, ldb2, vec2, C2)
    }
}

// dense NT GEMM (SIMT)
#define BM 128
#define BN 128
#define BK 16
__global__ __launch_bounds__(256,2) void k_gemm_nt(
    const float* __restrict__ A, int lda,
    const float* __restrict__ W, int K, const float* __restrict__ bias,
    float* __restrict__ Cc, int ldc, int act)
{
    int n0 = blockIdx.x * BN;
    int m0 = blockIdx.y * BM;
    __shared__ float As[2][BK][BM];
    __shared__ float Bs[2][BK][BN];
    int tid  = threadIdx.x;
    int arow = tid >> 1;
    int acol = (tid & 1) * 8;
    int ty = tid >> 4, tx = tid & 15;

    const float* aptr = A + (size_t)(m0+arow)*lda + acol;
    const float* wptr = W + (size_t)(n0+arow)*K   + acol;

    float4 a0 = *(const float4*)(aptr);
    float4 a1 = *(const float4*)(aptr + 4);
    float4 w0 = *(const float4*)(wptr);
    float4 w1 = *(const float4*)(wptr + 4);
    As[0][acol+0][arow]=a0.x; As[0][acol+1][arow]=a0.y; As[0][acol+2][arow]=a0.z; As[0][acol+3][arow]=a0.w;
    As[0][acol+4][arow]=a1.x; As[0][acol+5][arow]=a1.y; As[0][acol+6][arow]=a1.z; As[0][acol+7][arow]=a1.w;
    Bs[0][acol+0][arow]=w0.x; Bs[0][acol+1][arow]=w0.y; Bs[0][acol+2][arow]=w0.z; Bs[0][acol+3][arow]=w0.w;
    Bs[0][acol+4][arow]=w1.x; Bs[0][acol+5][arow]=w1.y; Bs[0][acol+6][arow]=w1.z; Bs[0][acol+7][arow]=w1.w;
    __syncthreads();

    float acc[8][8] = {};
    const int ntile = K/BK;
    for (int t = 0; t < ntile; t++){
        int cur = t & 1;
        if (t+1 < ntile){
            a0 = *(const float4*)(aptr + (t+1)*BK);
            a1 = *(const float4*)(aptr + (t+1)*BK + 4);
            w0 = *(const float4*)(wptr + (t+1)*BK);
            w1 = *(const float4*)(wptr + (t+1)*BK + 4);
        }
        #pragma unroll
        for (int k=0;k<BK;k++){
            float4 fa0 = *(const float4*)&As[cur][k][ty*4];
            float4 fa1 = *(const float4*)&As[cur][k][64+ty*4];
            float4 fb0 = *(const float4*)&Bs[cur][k][tx*4];
            float4 fb1 = *(const float4*)&Bs[cur][k][64+tx*4];
            float ar[8] = {fa0.x,fa0.y,fa0.z,fa0.w,fa1.x,fa1.y,fa1.z,fa1.w};
            float br[8] = {fb0.x,fb0.y,fb0.z,fb0.w,fb1.x,fb1.y,fb1.z,fb1.w};
            #pragma unroll
            for (int m=0;m<8;m++)
                #pragma unroll
                for (int n=0;n<8;n++)
                    acc[m][n] = fmaf(ar[m], br[n], acc[m][n]);
        }
        if (t+1 < ntile){
            int nxt = cur ^ 1;
            As[nxt][acol+0][arow]=a0.x; As[nxt][acol+1][arow]=a0.y; As[nxt][acol+2][arow]=a0.z; As[nxt][acol+3][arow]=a0.w;
            As[nxt][acol+4][arow]=a1.x; As[nxt][acol+5][arow]=a1.y; As[nxt][acol+6][arow]=a1.z; As[nxt][acol+7][arow]=a1.w;
            Bs[nxt][acol+0][arow]=w0.x; Bs[nxt][acol+1][arow]=w0.y; Bs[nxt][acol+2][arow]=w0.z; Bs[nxt][acol+3][arow]=w0.w;
            Bs[nxt][acol+4][arow]=w1.x; Bs[nxt][acol+5][arow]=w1.y; Bs[nxt][acol+6][arow]=w1.z; Bs[nxt][acol+7][arow]=w1.w;
            __syncthreads();
        }
    }
    #pragma unroll
    for (int mh=0; mh<2; mh++)
    #pragma unroll
    for (int mi=0; mi<4; mi++){
        int m = mh*4+mi;
        size_t gi = (size_t)(m0 + mh*64 + ty*4 + mi);
        float* outr = Cc + gi*(size_t)ldc + n0;
        #pragma unroll
        for (int nh=0; nh<2; nh++){
            int colb = nh*64 + tx*4;
            float4 bs = *(const float4*)(bias + n0 + colb);
            float4 o;
            o.x = acc[m][nh*4+0] + bs.x;
            o.y = acc[m][nh*4+1] + bs.y;
            o.z = acc[m][nh*4+2] + bs.z;
            o.w = acc[m][nh*4+3] + bs.w;
            if (act == 1){
                o.x=leakyf(o.x); o.y=leakyf(o.y); o.z=leakyf(o.z); o.w=leakyf(o.w);
            } else if (act == 2){
                o.x=tanhf(o.x)*40.f; o.y=tanhf(o.y)*40.f; o.z=tanhf(o.z)*40.f; o.w=tanhf(o.w)*40.f;
            }
            *(float4*)(outr + colb) = o;
        }
    }
}

// channel attention + weighted mean over 4 channels
__global__ void k_attn(int off, const float* __restrict__ avec){
    int i = blockIdx.x, d = threadIdx.x;
    size_t b = (size_t)i*HD + d;
    float x  = d_hid[(size_t)i*768 + off + d];
    float c0 = d_g[b];
    float u1 = d_u1[b], u2 = d_u2[b], u4 = d_u4[b];
    float c1 = fabsf(x - u1), c2 = fabsf(u1 - u2), c3 = fabsf(u2 - u4);
    float ah = avec[256 + d];
    float e0 = fmaxf(c0, 0.f)*ah, e1 = c1*ah, e2 = c2*ah, e3 = c3*ah;
    #pragma unroll
    for (int o=16;o;o>>=1){
        e0 += __shfl_xor_sync(0xffffffffu, e0, o);
        e1 += __shfl_xor_sync(0xffffffffu, e1, o);
        e2 += __shfl_xor_sync(0xffffffffu, e2, o);
        e3 += __shfl_xor_sync(0xffffffffu, e3, o);
    }
    __shared__ float sred[4][8];
    __shared__ float tot[4];
    int w = d >> 5;
    if ((d & 31) == 0){ sred[0][w]=e0; sred[1][w]=e1; sred[2][w]=e2; sred[3][w]=e3; }
    __syncthreads();
    if (d < 4){
        float t = 0.f;
        #pragma unroll
        for (int ww=0; ww<8; ww++) t += sred[d][ww];
        tot[d] = t;
    }
    __syncthreads();
    float E0=tot[0], E1=tot[1], E2=tot[2], E3=tot[3];
    float m = fmaxf(fmaxf(E0,E1), fmaxf(E2,E3));
    float w0=__expf(E0-m), w1=__expf(E1-m), w2=__expf(E2-m), w3=__expf(E3-m);
    float inv = 0.25f / (w0+w1+w2+w3);
    d_hp[b] = inv * (w0*c0 + w1*c1 + w2*c2 + w3*c3);
}

// Threefry-2x32-20, key (0,42)
__device__ __forceinline__ void threefry(unsigned x0, unsigned x1, unsigned& o0, unsigned& o1){
    const unsigned ks0 = 0u, ks1 = 42u, ks2 = 0x1BD11BDAu ^ 42u;
    x0 += ks0; x1 += ks1;
#define TFR(r) { x0 += x1; x1 = (x1<<(r))|(x1>>(32-(r))); x1 ^= x0; }
    TFR(13) TFR(15) TFR(26) TFR(6)   x0+=ks1; x1+=ks2+1u;
    TFR(17) TFR(29) TFR(16) TFR(24)  x0+=ks2; x1+=ks0+2u;
    TFR(13) TFR(15) TFR(26) TFR(6)   x0+=ks0; x1+=ks1+3u;
    TFR(17) TFR(29) TFR(16) TFR(24)  x0+=ks1; x1+=ks2+4u;
    TFR(13) TFR(15) TFR(26) TFR(6)   x0+=ks2; x1+=ks0+5u;
#undef TFR
    o0 = x0; o1 = x1;
}

__device__ __forceinline__ float gumb(unsigned bits){
    float u = __uint_as_float((bits >> 9) | 0x3F800000u) - 1.0f;
    return -logf(-logf(u + 1e-20f) + 1e-20f) * 0.05f;
}

__global__ void k_z0(float* __restrict__ z0){
    unsigned t = blockIdx.x*256u + threadIdx.x;
    unsigned o0, o1;
    threefry(0u, t, o0, o1);
    z0[t] = (d_logits[t] + gumb(o0 ^ o1)) * 10.0f;
}

__global__ void k_zeroC(){ d_Cv[blockIdx.x*256 + threadIdx.x] = 0.f; }

__global__ void k_row_lse(const float* __restrict__ Z){
    int row  = blockIdx.x*8 + (threadIdx.x>>5);
    int lane = threadIdx.x & 31;
    int b    = row >> 10;
    const float* z = Z + (size_t)row*NNODE;
    const float* c = d_Cv + b*NNODE;
    float v[32];
    float m = -3.4e38f;
    #pragma unroll
    for (int k=0;k<32;k++){ v[k] = z[lane + 32*k] - c[lane + 32*k]; m = fmaxf(m, v[k]); }
    #pragma unroll
    for (int o=16;o;o>>=1) m = fmaxf(m, __shfl_xor_sync(0xffffffffu, m, o));
    float s = 0.f;
    #pragma unroll
    for (int k=0;k<32;k++) s += __expf(v[k] - m);
    #pragma unroll
    for (int o=16;o;o>>=1) s += __shfl_xor_sync(0xffffffffu, s, o);
    if (lane==0) d_Rv[row] = m + __logf(s);
}

__device__ __forceinline__ void online_lse(float v, float& m, float& s){
    if (v > m){ s = s*__expf(m - v) + 1.f; m = v; }
    else      { s += __expf(v - m); }
}
__device__ __forceinline__ void merge_lse(float& M, float& S, float mg, float sg){
    if (mg > M){ S = S*__expf(M - mg) + sg; M = mg; }
    else       { S += sg*__expf(mg - M); }
}

__global__ void k_col_lse(const float* __restrict__ Z){
    int b     = blockIdx.x >> 4;
    int chunk = blockIdx.x & 15;
    int cg    = threadIdx.x & 15;
    int rg    = threadIdx.x >> 4;
    __shared__ float rs[NNODE];
    for (int k=threadIdx.x; k<NNODE; k+=256) rs[k] = d_Rv[b*NNODE + k];
    __syncthreads();
    const float4* z = (const float4*)(Z + (size_t)b*NNODE*NNODE) + chunk*16 + cg;
    float4 m[4], s[4];
    #pragma unroll
    for (int j=0;j<4;j++){
        m[j] = make_float4(-3.4e38f,-3.4e38f,-3.4e38f,-3.4e38f);
        s[j] = make_float4(0.f,0.f,0.f,0.f);
    }
    int i0 = rg*64;
    for (int i=i0; i<i0+64; i+=8){
        float4 v[8]; float r[8];
        #pragma unroll
        for (int j=0;j<8;j++){ v[j] = z[(size_t)(i+j)*256]; r[j] = rs[i+j]; }
        #pragma unroll
        for (int j=0;j<8;j++){
            int st = j & 3;
            online_lse(v[j].x - r[j], m[st].x, s[st].x);
            online_lse(v[j].y - r[j], m[st].y, s[st].y);
            online_lse(v[j].z - r[j], m[st].z, s[st].z);
            online_lse(v[j].w - r[j], m[st].w, s[st].w);
        }
    }
    float4 M = m[0], S = s[0];
    #pragma unroll
    for (int j=1;j<4;j++){
        merge_lse(M.x, S.x, m[j].x, s[j].x);
        merge_lse(M.y, S.y, m[j].y, s[j].y);
        merge_lse(M.z, S.z, m[j].z, s[j].z);
        merge_lse(M.w, S.w, m[j].w, s[j].w);
    }
    __shared__ float4 sm16[16][16], ss16[16][16];
    sm16[rg][cg] = M; ss16[rg][cg] = S;
    __syncthreads();
    if (rg == 0){
        #pragma unroll
        for (int g=1; g<16; g++){
            float4 mg = sm16[g][cg], sg = ss16[g][cg];
            merge_lse(M.x, S.x, mg.x, sg.x);
            merge_lse(M.y, S.y, mg.y, sg.y);
            merge_lse(M.z, S.z, mg.z, sg.z);
            merge_lse(M.w, S.w, mg.w, sg.w);
        }
        int j = b*NNODE + chunk*64 + cg*4;
        d_Cv[j+0] = M.x + __logf(S.x);
        d_Cv[j+1] = M.y + __logf(S.y);
        d_Cv[j+2] = M.z + __logf(S.z);
        d_Cv[j+3] = M.w + __logf(S.w);
    }
}

__global__ void k_col_T(const float* __restrict__ Z){
    int b     = blockIdx.x >> 4;
    int chunk = blockIdx.x & 15;
    int cg    = threadIdx.x & 15;
    int rg    = threadIdx.x >> 4;
    __shared__ float rs[NNODE];
    for (int k=threadIdx.x; k<NNODE; k+=256) rs[k] = d_Rv[b*NNODE + k];
    __syncthreads();
    float4 cj = *((const float4*)(d_Cv + b*NNODE) + chunk*16 + cg);
    const float4* z = (const float4*)(Z + (size_t)b*NNODE*NNODE) + chunk*16 + cg;
    float4 s = {0.f,0.f,0.f,0.f};
    int i0 = rg*64;
    for (int i=i0; i<i0+64; i+=8){
        float4 v[8]; float r[8];
        #pragma unroll
        for (int j=0;j<8;j++){ v[j] = z[(size_t)(i+j)*256]; r[j] = rs[i+j]; }
        #pragma unroll
        for (int j=0;j<8;j++){
            s.x += __expf(v[j].x - r[j] - cj.x);
            s.y += __expf(v[j].y - r[j] - cj.y);
            s.z += __expf(v[j].z - r[j] - cj.z);
            s.w += __expf(v[j].w - r[j] - cj.w);
        }
    }
    __shared__ float4 ss16[16][16];
    ss16[rg][cg] = s;
    __syncthreads();
    if (rg == 0){
        #pragma unroll
        for (int g=1; g<16; g++){
            float4 sg = ss16[g][cg];
            s.x += sg.x; s.y += sg.y; s.z += sg.z; s.w += sg.w;
        }
        int j = b*NNODE + chunk*64 + cg*4;
        d_Tv[j+0]=s.x; d_Tv[j+1]=s.y; d_Tv[j+2]=s.z; d_Tv[j+3]=s.w;
    }
}

__global__ void k_final(const float* __restrict__ Z, float* __restrict__ P){
    size_t t = (size_t)blockIdx.x*256 + threadIdx.x;
    int row = (int)(t >> 10);
    int b   = row >> 10;
    int j   = (int)(t & 1023);
    P[t] = __expf(Z[t] - d_Rv[row] - d_Cv[b*NNODE + j]) / d_Tv[b*NNODE + j];
}

extern "C" void kernel_launch(void* const* d_in, const int* in_sizes, int n_in,
                              void* d_out, int out_size) {
    const float* X      = (const float*)d_in[0];
    const float* adj    = (const float*)d_in[1];
    const float* w_in   = (const float*)d_in[2];
    const float* b_in   = (const float*)d_in[3];
    const float* cw1    = (const float*)d_in[4];
    const float* cb1    = (const float*)d_in[5];
    const float* cw2    = (const float*)d_in[6];
    const float* cb2    = (const float*)d_in[7];
    const float* ca     = (const float*)d_in[8];
    const float* m1w    = (const float*)d_in[9];
    const float* m1b    = (const float*)d_in[10];
    const float* m2w    = (const float*)d_in[11];
    const float* m2b    = (const float*)d_in[12];
    float* Pout = (float*)d_out;
    float* Z0   = Pout + (size_t)TOTEL;

    float *hid, *hs, *g, *u1, *u2, *u3, *u4, *hp, *mid, *lg;
    cudaGetSymbolAddress((void**)&hid, d_hid);
    cudaGetSymbolAddress((void**)&hs,  d_hs);
    cudaGetSymbolAddress((void**)&g,   d_g);
    cudaGetSymbolAddress((void**)&u1,  d_u1);
    cudaGetSymbolAddress((void**)&u2,  d_u2);
    cudaGetSymbolAddress((void**)&u3,  d_u3);
    cudaGetSymbolAddress((void**)&u4,  d_u4);
    cudaGetSymbolAddress((void**)&hp,  d_hp);
    cudaGetSymbolAddress((void**)&mid, d_mid);
    cudaGetSymbolAddress((void**)&lg,  d_logits);
    float *dis, *invdeg;
    cudaGetSymbolAddress((void**)&dis,    d_dis);
    cudaGetSymbolAddress((void**)&invdeg, d_invdeg);

    cudaFuncSetAttribute(k_mma, cudaFuncAttributeMaxDynamicSharedMemorySize, SM2TOT);
    cudaFuncSetAttribute(k_mma_dual, cudaFuncAttributeMaxDynamicSharedMemorySize, SM2TOT);

    k_adj_stats<<<NROWS/8, 256>>>(adj);

    // h0 = X @ w_in^T + b_in
    k_gemm_nt<<<dim3(2,128), 256>>>(X, 128, w_in, 128, b_in, hid, 768, 0);

    dim3 tg(2, 8, 16);
    dim3 tgd(4, 8, 16);
    for (int l = 0; l < 2; l++){
        int off  = 256*l;
        int offn = 256*(l+1);
        k_scale_hs<<<NROWS*HD/256, 256>>>(off);
        k_mma_dual<<<tgd, 256, SM2TOT>>>(adj, hs, g, dis, hid+off, 768, u1, invdeg);
        k_mma<<<tg, 256, SM2TOT>>>(adj, u1, 256, u2, 2, u1, 256, invdeg);
        k_mma<<<tg, 256, SM2TOT>>>(adj, u2, 256, u3, 2, u2, 256, invdeg);
        k_mma<<<tg, 256, SM2TOT>>>(adj, u3, 256, u4, 2, u3, 256, invdeg);
        k_attn<<<NROWS, 256>>>(off, ca + l*512);
        k_gemm_nt<<<dim3(2,128), 256>>>(hp,  256, cw1 + l*65536, 256, cb1 + l*256, mid, 256, 1);
        k_gemm_nt<<<dim3(2,128), 256>>>(mid, 256, cw2 + l*65536, 256, cb2 + l*256, hid + offn, 768, 1);
    }

    // mlp1 + mlp2
    k_gemm_nt<<<dim3(2,128), 256>>>(hid, 768, m1w, 768, m1b, mid, 256, 1);
    k_gemm_nt<<<dim3(8,128), 256>>>(mid, 256, m2w, 256, m2b, lg, 1024, 2);

    // Z0 = (logits + gumbel)/tau  (gsinit output)
    k_z0<<<TOTEL/256, 256>>>(Z0);

    // Sinkhorn: rank-1 log-domain state (R, C)
    k_zeroC<<<NROWS/256, 256>>>();
    for (int it = 0; it < 20; it++){
        k_row_lse<<<NROWS/8, 256>>>(Z0);
        k_col_lse<<<256, 256>>>(Z0);
    }
    k_row_lse<<<NROWS/8, 256>>>(Z0);
    k_col_T  <<<256, 256>>>(Z0);
    k_final  <<<TOTEL/256, 256>>>(Z0, Pout);
}

// round 15
// speedup vs baseline: 1.1170x; 1.1170x over previous
#include <cuda_runtime.h>
#include <cuda_bf16.h>
#include <cstdint>
#include <math.h>

#define NBATCH 16
#define NNODE  1024
#define HD     256
#define NROWS  (NBATCH*NNODE)
#define TOTEL  16777216

__device__ float d_hid[NROWS*768];
__device__ float d_hs [NROWS*HD];
__device__ float d_g  [NROWS*HD];
__device__ float d_u1 [NROWS*HD];
__device__ float d_u2 [NROWS*HD];
__device__ float d_u3 [NROWS*HD];
__device__ float d_u4 [NROWS*HD];
__device__ float d_hp [NROWS*HD];
__device__ float d_mid[NROWS*HD];
__device__ float d_logits[TOTEL];
__device__ float d_adjhi[TOTEL];
__device__ float d_adjlo[TOTEL];
__device__ float d_dis[NROWS];
__device__ float d_invdeg[NROWS];
__device__ float d_Rv[NROWS];
__device__ float d_Cv[NROWS];
__device__ float d_Tv[NROWS];

__device__ __forceinline__ float leakyf(float x){ return x > 0.f ? x : 0.01f*x; }

__global__ void k_adj_stats(const float* __restrict__ adj){
    int row  = blockIdx.x*8 + (threadIdx.x>>5);
    int lane = threadIdx.x & 31;
    const float* a = adj + (size_t)row*NNODE;
    float s = 0.f;
    #pragma unroll
    for (int k=0;k<32;k++) s += a[lane + 32*k];
    #pragma unroll
    for (int o=16;o;o>>=1) s += __shfl_xor_sync(0xffffffffu, s, o);
    if (lane==0){ d_dis[row] = rsqrtf(s + 1.f); d_invdeg[row] = 1.f/s; }
}

__global__ void k_scale_hs(int off){
    int idx = blockIdx.x*256 + threadIdx.x;
    int row = idx >> 8, col = idx & 255;
    d_hs[idx] = d_dis[row] * d_hid[(size_t)row*768 + off + col];
}

// ---------------- 3xTF32 helpers ----------------
__device__ __forceinline__ float2 split2(float v){
    uint32_t h;
    asm("cvt.rna.tf32.f32 %0, %1;" : "=r"(h) : "f"(v));
    float hf = __uint_as_float(h);
    float r = v - hf;
    uint32_t l;
    asm("cvt.rna.tf32.f32 %0, %1;" : "=r"(l) : "f"(r));
    return make_float2(hf, __uint_as_float(l));
}
__device__ __forceinline__ void mma_tf32(float* c,
    uint32_t a0, uint32_t a1, uint32_t a2, uint32_t a3,
    uint32_t b0, uint32_t b1){
    asm volatile(
        "mma.sync.aligned.m16n8k8.row.col.f32.tf32.tf32.f32 "
        "{%0,%1,%2,%3}, {%4,%5,%6,%7}, {%8,%9}, {%0,%1,%2,%3};"
        : "+f"(c[0]), "+f"(c[1]), "+f"(c[2]), "+f"(c[3])
        : "r"(a0), "r"(a1), "r"(a2), "r"(a3), "r"(b0), "r"(b1));
}
#define U(x) __float_as_uint(x)

// pre-split adj into tf32 hi/lo fp32 planes
__global__ void k_splitA(const float* __restrict__ adj){
    size_t i = (size_t)blockIdx.x*256 + threadIdx.x;
    float2 p = split2(adj[i]);
    d_adjhi[i] = p.x; d_adjlo[i] = p.y;
}

#define PAD 132
#define PLANE (2*16*PAD)                 /* one hi or lo plane, 2 buffers, floats */
#define SMTOT (4*PLANE*4)                /* Ah, Al, Bh, Bl = 67584 bytes */

// ---------------- shared mainloop + epilogue macros (R13 structure) ----------------
#define MMA_MAINLOOP(AHPTR, ALPTR, BPTR, LDB)                                                \
    float (*Ah)[16][PAD] = (float(*)[16][PAD])(smf);                                         \
    float (*Al)[16][PAD] = (float(*)[16][PAD])(smf + PLANE);                                 \
    float (*Bh)[16][PAD] = (float(*)[16][PAD])(smf + 2*PLANE);                               \
    float (*Bl)[16][PAD] = (float(*)[16][PAD])(smf + 3*PLANE);                               \
    {                                                                                        \
        float4 h0 = *(const float4*)(AHPTR);                                                 \
        float4 h1 = *(const float4*)(AHPTR + 4);                                             \
        float4 l0 = *(const float4*)(ALPTR);                                                 \
        float4 l1 = *(const float4*)(ALPTR + 4);                                             \
        float4 b0 = *(const float4*)(BPTR);                                                  \
        float4 b1 = *(const float4*)(BPTR + 4);                                              \
        Ah[0][acol+0][arow]=h0.x; Ah[0][acol+1][arow]=h0.y; Ah[0][acol+2][arow]=h0.z; Ah[0][acol+3][arow]=h0.w; \
        Ah[0][acol+4][arow]=h1.x; Ah[0][acol+5][arow]=h1.y; Ah[0][acol+6][arow]=h1.z; Ah[0][acol+7][arow]=h1.w; \
        Al[0][acol+0][arow]=l0.x; Al[0][acol+1][arow]=l0.y; Al[0][acol+2][arow]=l0.z; Al[0][acol+3][arow]=l0.w; \
        Al[0][acol+4][arow]=l1.x; Al[0][acol+5][arow]=l1.y; Al[0][acol+6][arow]=l1.z; Al[0][acol+7][arow]=l1.w; \
        float2 s;                                                                            \
        s=split2(b0.x); Bh[0][brow][bcol+0]=s.x; Bl[0][brow][bcol+0]=s.y;                    \
        s=split2(b0.y); Bh[0][brow][bcol+1]=s.x; Bl[0][brow][bcol+1]=s.y;                    \
        s=split2(b0.z); Bh[0][brow][bcol+2]=s.x; Bl[0][brow][bcol+2]=s.y;                    \
        s=split2(b0.w); Bh[0][brow][bcol+3]=s.x; Bl[0][brow][bcol+3]=s.y;                    \
        s=split2(b1.x); Bh[0][brow][bcol+4]=s.x; Bl[0][brow][bcol+4]=s.y;                    \
        s=split2(b1.y); Bh[0][brow][bcol+5]=s.x; Bl[0][brow][bcol+5]=s.y;                    \
        s=split2(b1.z); Bh[0][brow][bcol+6]=s.x; Bl[0][brow][bcol+6]=s.y;                    \
        s=split2(b1.w); Bh[0][brow][bcol+7]=s.x; Bl[0][brow][bcol+7]=s.y;                    \
    }                                                                                        \
    __syncthreads();                                                                         \
    const int ntile = NNODE/16;                                                              \
    for (int t = 0; t < ntile; t++){                                                         \
        int cur = t & 1;                                                                     \
        float4 ph0, ph1, pl0, pl1, pb0, pb1;                                                 \
        if (t+1 < ntile){                                                                    \
            ph0 = *(const float4*)((AHPTR) + (t+1)*16);                                      \
            ph1 = *(const float4*)((AHPTR) + (t+1)*16 + 4);                                  \
            pl0 = *(const float4*)((ALPTR) + (t+1)*16);                                      \
            pl1 = *(const float4*)((ALPTR) + (t+1)*16 + 4);                                  \
            pb0 = *(const float4*)((BPTR) + (size_t)(t+1)*16*(LDB));                         \
            pb1 = *(const float4*)((BPTR) + (size_t)(t+1)*16*(LDB) + 4);                     \
        }                                                                                    \
        _Pragma("unroll")                                                                    \
        for (int k8 = 0; k8 < 16; k8 += 8){                                                  \
            float fh[2][4], fl[2][4];                                                        \
            _Pragma("unroll")                                                                \
            for (int f = 0; f < 2; f++){                                                     \
                int mb = wm + f*16 + lr;                                                     \
                fh[f][0] = Ah[cur][k8+lc][mb];   fl[f][0] = Al[cur][k8+lc][mb];              \
                fh[f][1] = Ah[cur][k8+lc][mb+8]; fl[f][1] = Al[cur][k8+lc][mb+8];            \
                fh[f][2] = Ah[cur][k8+lc+4][mb]; fl[f][2] = Al[cur][k8+lc+4][mb];            \
                fh[f][3] = Ah[cur][k8+lc+4][mb+8]; fl[f][3] = Al[cur][k8+lc+4][mb+8];        \
            }                                                                                \
            _Pragma("unroll")                                                                \
            for (int gh = 0; gh < 2; gh++){                                                  \
                float gbh[4][2], gbl[4][2];                                                  \
                _Pragma("unroll")                                                            \
                for (int g = 0; g < 4; g++){                                                 \
                    int n = wn + gh*32 + g*8 + lr;                                           \
                    gbh[g][0] = Bh[cur][k8+lc][n];   gbl[g][0] = Bl[cur][k8+lc][n];          \
                    gbh[g][1] = Bh[cur][k8+lc+4][n]; gbl[g][1] = Bl[cur][k8+lc+4][n];        \
                }                                                                            \
                _Pragma("unroll")                                                            \
                for (int f = 0; f < 2; f++)                                                  \
                _Pragma("unroll")                                                            \
                for (int g = 0; g < 4; g++){                                                 \
                    float* c = acc[f][gh*4+g];                                               \
                    mma_tf32(c, U(fh[f][0]),U(fh[f][1]),U(fh[f][2]),U(fh[f][3]),             \
                                U(gbh[g][0]),U(gbh[g][1]));                                  \
                    mma_tf32(c, U(fh[f][0]),U(fh[f][1]),U(fh[f][2]),U(fh[f][3]),             \
                                U(gbl[g][0]),U(gbl[g][1]));                                  \
                    mma_tf32(c, U(fl[f][0]),U(fl[f][1]),U(fl[f][2]),U(fl[f][3]),             \
                                U(gbh[g][0]),U(gbh[g][1]));                                  \
                }                                                                            \
            }                                                                                \
        }                                                                                    \
        if (t+1 < ntile){                                                                    \
            int nxt = cur ^ 1;                                                               \
            Ah[nxt][acol+0][arow]=ph0.x; Ah[nxt][acol+1][arow]=ph0.y; Ah[nxt][acol+2][arow]=ph0.z; Ah[nxt][acol+3][arow]=ph0.w; \
            Ah[nxt][acol+4][arow]=ph1.x; Ah[nxt][acol+5][arow]=ph1.y; Ah[nxt][acol+6][arow]=ph1.z; Ah[nxt][acol+7][arow]=ph1.w; \
            Al[nxt][acol+0][arow]=pl0.x; Al[nxt][acol+1][arow]=pl0.y; Al[nxt][acol+2][arow]=pl0.z; Al[nxt][acol+3][arow]=pl0.w; \
            Al[nxt][acol+4][arow]=pl1.x; Al[nxt][acol+5][arow]=pl1.y; Al[nxt][acol+6][arow]=pl1.z; Al[nxt][acol+7][arow]=pl1.w; \
            float2 s;                                                                        \
            s=split2(pb0.x); Bh[nxt][brow][bcol+0]=s.x; Bl[nxt][brow][bcol+0]=s.y;           \
            s=split2(pb0.y); Bh[nxt][brow][bcol+1]=s.x; Bl[nxt][brow][bcol+1]=s.y;           \
            s=split2(pb0.z); Bh[nxt][brow][bcol+2]=s.x; Bl[nxt][brow][bcol+2]=s.y;           \
            s=split2(pb0.w); Bh[nxt][brow][bcol+3]=s.x; Bl[nxt][brow][bcol+3]=s.y;           \
            s=split2(pb1.x); Bh[nxt][brow][bcol+4]=s.x; Bl[nxt][brow][bcol+4]=s.y;           \
            s=split2(pb1.y); Bh[nxt][brow][bcol+5]=s.x; Bl[nxt][brow][bcol+5]=s.y;           \
            s=split2(pb1.z); Bh[nxt][brow][bcol+6]=s.x; Bl[nxt][brow][bcol+6]=s.y;           \
            s=split2(pb1.w); Bh[nxt][brow][bcol+7]=s.x; Bl[nxt][brow][bcol+7]=s.y;           \
            __syncthreads();                                                                 \
        }                                                                                    \
    }

#define MMA_EPILOGUE(MODE, AUX, LDAUX, VEC, OUT)                                             \
    _Pragma("unroll")                                                                        \
    for (int f = 0; f < 2; f++){                                                             \
        int r0 = m0 + wm + f*16 + lr;                                                        \
        size_t gi0 = (size_t)(bb*NNODE + r0);                                                \
        size_t gi1 = gi0 + 8;                                                                \
        float dv0 = (VEC)[gi0], dv1 = (VEC)[gi1];                                            \
        const float* aux0 = (AUX) + gi0*(size_t)(LDAUX) + n0 + wn;                           \
        const float* aux1 = (AUX) + gi1*(size_t)(LDAUX) + n0 + wn;                           \
        float* out0 = (OUT) + gi0*(size_t)256 + n0 + wn;                                     \
        float* out1 = (OUT) + gi1*(size_t)256 + n0 + wn;                                     \
        _Pragma("unroll")                                                                    \
        for (int g = 0; g < 8; g++){                                                         \
            int c = g*8 + lc*2;                                                              \
            float2 ax0 = *(const float2*)(aux0 + c);                                         \
            float2 ax1 = *(const float2*)(aux1 + c);                                         \
            float* a = acc[f][g];                                                            \
            float2 o0, o1;                                                                   \
            if ((MODE) == 1){                                                                \
                o0.x = leakyf(dv0*(a[0]+ax0.x)); o0.y = leakyf(dv0*(a[1]+ax0.y));            \
                o1.x = leakyf(dv1*(a[2]+ax1.x)); o1.y = leakyf(dv1*(a[3]+ax1.y));            \
            } else {                                                                         \
                o0.x = 0.5f*(ax0.x + a[0]*dv0); o0.y = 0.5f*(ax0.y + a[1]*dv0);              \
                o1.x = 0.5f*(ax1.x + a[2]*dv1); o1.y = 0.5f*(ax1.y + a[3]*dv1);              \
            }                                                                                \
            *(float2*)(out0 + c) = o0;                                                       \
            *(float2*)(out1 + c) = o1;                                                       \
        }                                                                                    \
    }

// batched adj GEMM on tensor cores (3xTF32, A pre-split in gmem)
__global__ __launch_bounds__(256,2) void k_mma(
    const float* __restrict__ B, int ldb,
    float* __restrict__ Cc, int mode,
    const float* __restrict__ aux, int ldaux, const float* __restrict__ vec)
{
    extern __shared__ float smf[];
    int bb = blockIdx.z;
    int n0 = blockIdx.x * 128;
    int m0 = blockIdx.y * 128;
    int tid  = threadIdx.x;
    int wid  = tid >> 5, lane = tid & 31;
    int lr = lane >> 2, lc = lane & 3;
    int wm = (wid & 3) * 32;
    int wn = (wid >> 2) * 64;
    int arow = tid >> 1, acol = (tid & 1)*8;
    int brow = tid >> 4, bcol = (tid & 15)*8;

    const float* ahptr = d_adjhi + (size_t)bb*NNODE*NNODE + (size_t)(m0+arow)*NNODE + acol;
    const float* alptr = d_adjlo + (size_t)bb*NNODE*NNODE + (size_t)(m0+arow)*NNODE + acol;
    const float* bptr  = B + (size_t)(bb*NNODE + brow)*ldb + n0 + bcol;
    float acc[2][8][4] = {};
    MMA_MAINLOOP(ahptr, alptr, bptr, ldb)
    MMA_EPILOGUE(mode, aux, ldaux, vec, Cc)
}

// fused: blockIdx.x 0-1 -> GCN (B1->C1, mode1), 2-3 -> lazy walk (B2->C2, mode2)
__global__ __launch_bounds__(256,2) void k_mma_dual(
    const float* __restrict__ B1, float* __restrict__ C1, const float* __restrict__ vec1,
    const float* __restrict__ B2, int ldb2, float* __restrict__ C2, const float* __restrict__ vec2)
{
    extern __shared__ float smf[];
    int bb = blockIdx.z;
    int half = blockIdx.x >> 1;
    int n0 = (blockIdx.x & 1) * 128;
    int m0 = blockIdx.y * 128;
    int tid  = threadIdx.x;
    int wid  = tid >> 5, lane = tid & 31;
    int lr = lane >> 2, lc = lane & 3;
    int wm = (wid & 3) * 32;
    int wn = (wid >> 2) * 64;
    int arow = tid >> 1, acol = (tid & 1)*8;
    int brow = tid >> 4, bcol = (tid & 15)*8;

    const float* B = half ? B2 : B1;
    int ldb        = half ? ldb2 : 256;
    const float* ahptr = d_adjhi + (size_t)bb*NNODE*NNODE + (size_t)(m0+arow)*NNODE + acol;
    const float* alptr = d_adjlo + (size_t)bb*NNODE*NNODE + (size_t)(m0+arow)*NNODE + acol;
    const float* bptr  = B + (size_t)(bb*NNODE + brow)*ldb + n0 + bcol;
    float acc[2][8][4] = {};
    MMA_MAINLOOP(ahptr, alptr, bptr, ldb)
    if (half == 0){
        MMA_EPILOGUE(1, B1, 256, vec1, C1)
    } else {
        MMA_EPILOGUE(2, B2, ldb2, vec2, C2)
    }
}

// dense NT GEMM (SIMT)
#define BM 128
#define BN 128
#define BK 16
__global__ __launch_bounds__(256,2) void k_gemm_nt(
    const float* __restrict__ A, int lda,
    const float* __restrict__ W, int K, const float* __restrict__ bias,
    float* __restrict__ Cc, int ldc, int act)
{
    int n0 = blockIdx.x * BN;
    int m0 = blockIdx.y * BM;
    __shared__ float As[2][BK][BM];
    __shared__ float Bs[2][BK][BN];
    int tid  = threadIdx.x;
    int arow = tid >> 1;
    int acol = (tid & 1) * 8;
    int ty = tid >> 4, tx = tid & 15;

    const float* aptr = A + (size_t)(m0+arow)*lda + acol;
    const float* wptr = W + (size_t)(n0+arow)*K   + acol;

    float4 a0 = *(const float4*)(aptr);
    float4 a1 = *(const float4*)(aptr + 4);
    float4 w0 = *(const float4*)(wptr);
    float4 w1 = *(const float4*)(wptr + 4);
    As[0][acol+0][arow]=a0.x; As[0][acol+1][arow]=a0.y; As[0][acol+2][arow]=a0.z; As[0][acol+3][arow]=a0.w;
    As[0][acol+4][arow]=a1.x; As[0][acol+5][arow]=a1.y; As[0][acol+6][arow]=a1.z; As[0][acol+7][arow]=a1.w;
    Bs[0][acol+0][arow]=w0.x; Bs[0][acol+1][arow]=w0.y; Bs[0][acol+2][arow]=w0.z; Bs[0][acol+3][arow]=w0.w;
    Bs[0][acol+4][arow]=w1.x; Bs[0][acol+5][arow]=w1.y; Bs[0][acol+6][arow]=w1.z; Bs[0][acol+7][arow]=w1.w;
    __syncthreads();

    float acc[8][8] = {};
    const int ntile = K/BK;
    for (int t = 0; t < ntile; t++){
        int cur = t & 1;
        if (t+1 < ntile){
            a0 = *(const float4*)(aptr + (t+1)*BK);
            a1 = *(const float4*)(aptr + (t+1)*BK + 4);
            w0 = *(const float4*)(wptr + (t+1)*BK);
            w1 = *(const float4*)(wptr + (t+1)*BK + 4);
        }
        #pragma unroll
        for (int k=0;k<BK;k++){
            float4 fa0 = *(const float4*)&As[cur][k][ty*4];
            float4 fa1 = *(const float4*)&As[cur][k][64+ty*4];
            float4 fb0 = *(const float4*)&Bs[cur][k][tx*4];
            float4 fb1 = *(const float4*)&Bs[cur][k][64+tx*4];
            float ar[8] = {fa0.x,fa0.y,fa0.z,fa0.w,fa1.x,fa1.y,fa1.z,fa1.w};
            float br[8] = {fb0.x,fb0.y,fb0.z,fb0.w,fb1.x,fb1.y,fb1.z,fb1.w};
            #pragma unroll
            for (int m=0;m<8;m++)
                #pragma unroll
                for (int n=0;n<8;n++)
                    acc[m][n] = fmaf(ar[m], br[n], acc[m][n]);
        }
        if (t+1 < ntile){
            int nxt = cur ^ 1;
            As[nxt][acol+0][arow]=a0.x; As[nxt][acol+1][arow]=a0.y; As[nxt][acol+2][arow]=a0.z; As[nxt][acol+3][arow]=a0.w;
            As[nxt][acol+4][arow]=a1.x; As[nxt][acol+5][arow]=a1.y; As[nxt][acol+6][arow]=a1.z; As[nxt][acol+7][arow]=a1.w;
            Bs[nxt][acol+0][arow]=w0.x; Bs[nxt][acol+1][arow]=w0.y; Bs[nxt][acol+2][arow]=w0.z; Bs[nxt][acol+3][arow]=w0.w;
            Bs[nxt][acol+4][arow]=w1.x; Bs[nxt][acol+5][arow]=w1.y; Bs[nxt][acol+6][arow]=w1.z; Bs[nxt][acol+7][arow]=w1.w;
            __syncthreads();
        }
    }
    #pragma unroll
    for (int mh=0; mh<2; mh++)
    #pragma unroll
    for (int mi=0; mi<4; mi++){
        int m = mh*4+mi;
        size_t gi = (size_t)(m0 + mh*64 + ty*4 + mi);
        float* outr = Cc + gi*(size_t)ldc + n0;
        #pragma unroll
        for (int nh=0; nh<2; nh++){
            int colb = nh*64 + tx*4;
            float4 bs = *(const float4*)(bias + n0 + colb);
            float4 o;
            o.x = acc[m][nh*4+0] + bs.x;
            o.y = acc[m][nh*4+1] + bs.y;
            o.z = acc[m][nh*4+2] + bs.z;
            o.w = acc[m][nh*4+3] + bs.w;
            if (act == 1){
                o.x=leakyf(o.x); o.y=leakyf(o.y); o.z=leakyf(o.z); o.w=leakyf(o.w);
            } else if (act == 2){
                o.x=tanhf(o.x)*40.f; o.y=tanhf(o.y)*40.f; o.z=tanhf(o.z)*40.f; o.w=tanhf(o.w)*40.f;
            }
            *(float4*)(outr + colb) = o;
        }
    }
}

// channel attention + weighted mean over 4 channels
__global__ void k_attn(int off, const float* __restrict__ avec){
    int i = blockIdx.x, d = threadIdx.x;
    size_t b = (size_t)i*HD + d;
    float x  = d_hid[(size_t)i*768 + off + d];
    float c0 = d_g[b];
    float u1 = d_u1[b], u2 = d_u2[b], u4 = d_u4[b];
    float c1 = fabsf(x - u1), c2 = fabsf(u1 - u2), c3 = fabsf(u2 - u4);
    float ah = avec[256 + d];
    float e0 = fmaxf(c0, 0.f)*ah, e1 = c1*ah, e2 = c2*ah, e3 = c3*ah;
    #pragma unroll
    for (int o=16;o;o>>=1){
        e0 += __shfl_xor_sync(0xffffffffu, e0, o);
        e1 += __shfl_xor_sync(0xffffffffu, e1, o);
        e2 += __shfl_xor_sync(0xffffffffu, e2, o);
        e3 += __shfl_xor_sync(0xffffffffu, e3, o);
    }
    __shared__ float sred[4][8];
    __shared__ float tot[4];
    int w = d >> 5;
    if ((d & 31) == 0){ sred[0][w]=e0; sred[1][w]=e1; sred[2][w]=e2; sred[3][w]=e3; }
    __syncthreads();
    if (d < 4){
        float t = 0.f;
        #pragma unroll
        for (int ww=0; ww<8; ww++) t += sred[d][ww];
        tot[d] = t;
    }
    __syncthreads();
    float E0=tot[0], E1=tot[1], E2=tot[2], E3=tot[3];
    float m = fmaxf(fmaxf(E0,E1), fmaxf(E2,E3));
    float w0=__expf(E0-m), w1=__expf(E1-m), w2=__expf(E2-m), w3=__expf(E3-m);
    float inv = 0.25f / (w0+w1+w2+w3);
    d_hp[b] = inv * (w0*c0 + w1*c1 + w2*c2 + w3*c3);
}

// Threefry-2x32-20, key (0,42)
__device__ __forceinline__ void threefry(unsigned x0, unsigned x1, unsigned& o0, unsigned& o1){
    const unsigned ks0 = 0u, ks1 = 42u, ks2 = 0x1BD11BDAu ^ 42u;
    x0 += ks0; x1 += ks1;
#define TFR(r) { x0 += x1; x1 = (x1<<(r))|(x1>>(32-(r))); x1 ^= x0; }
    TFR(13) TFR(15) TFR(26) TFR(6)   x0+=ks1; x1+=ks2+1u;
    TFR(17) TFR(29) TFR(16) TFR(24)  x0+=ks2; x1+=ks0+2u;
    TFR(13) TFR(15) TFR(26) TFR(6)   x0+=ks0; x1+=ks1+3u;
    TFR(17) TFR(29) TFR(16) TFR(24)  x0+=ks1; x1+=ks2+4u;
    TFR(13) TFR(15) TFR(26) TFR(6)   x0+=ks2; x1+=ks0+5u;
#undef TFR
    o0 = x0; o1 = x1;
}

__device__ __forceinline__ float gumb(unsigned bits){
    float u = __uint_as_float((bits >> 9) | 0x3F800000u) - 1.0f;
    return -logf(-logf(u + 1e-20f) + 1e-20f) * 0.05f;
}

__global__ void k_z0(float* __restrict__ z0){
    unsigned t = blockIdx.x*256u + threadIdx.x;
    unsigned o0, o1;
    threefry(0u, t, o0, o1);
    z0[t] = (d_logits[t] + gumb(o0 ^ o1)) * 10.0f;
}

__global__ void k_zeroC(){ d_Cv[blockIdx.x*256 + threadIdx.x] = 0.f; }

__global__ void k_row_lse(const float* __restrict__ Z){
    int row  = blockIdx.x*8 + (threadIdx.x>>5);
    int lane = threadIdx.x & 31;
    int b    = row >> 10;
    const float* z = Z + (size_t)row*NNODE;
    const float* c = d_Cv + b*NNODE;
    float v[32];
    float m = -3.4e38f;
    #pragma unroll
    for (int k=0;k<32;k++){ v[k] = z[lane + 32*k] - c[lane + 32*k]; m = fmaxf(m, v[k]); }
    #pragma unroll
    for (int o=16;o;o>>=1) m = fmaxf(m, __shfl_xor_sync(0xffffffffu, m, o));
    float s = 0.f;
    #pragma unroll
    for (int k=0;k<32;k++) s += __expf(v[k] - m);
    #pragma unroll
    for (int o=16;o;o>>=1) s += __shfl_xor_sync(0xffffffffu, s, o);
    if (lane==0) d_Rv[row] = m + __logf(s);
}

__device__ __forceinline__ void online_lse(float v, float& m, float& s){
    if (v > m){ s = s*__expf(m - v) + 1.f; m = v; }
    else      { s += __expf(v - m); }
}
__device__ __forceinline__ void merge_lse(float& M, float& S, float mg, float sg){
    if (mg > M){ S = S*__expf(M - mg) + sg; M = mg; }
    else       { S += sg*__expf(mg - M); }
}

__global__ void k_col_lse(const float* __restrict__ Z){
    int b     = blockIdx.x >> 4;
    int chunk = blockIdx.x & 15;
    int cg    = threadIdx.x & 15;
    int rg    = threadIdx.x >> 4;
    __shared__ float rs[NNODE];
    for (int k=threadIdx.x; k<NNODE; k+=256) rs[k] = d_Rv[b*NNODE + k];
    __syncthreads();
    const float4* z = (const float4*)(Z + (size_t)b*NNODE*NNODE) + chunk*16 + cg;
    float4 m[4], s[4];
    #pragma unroll
    for (int j=0;j<4;j++){
        m[j] = make_float4(-3.4e38f,-3.4e38f,-3.4e38f,-3.4e38f);
        s[j] = make_float4(0.f,0.f,0.f,0.f);
    }
    int i0 = rg*64;
    for (int i=i0; i<i0+64; i+=8){
        float4 v[8]; float r[8];
        #pragma unroll
        for (int j=0;j<8;j++){ v[j] = z[(size_t)(i+j)*256]; r[j] = rs[i+j]; }
        #pragma unroll
        for (int j=0;j<8;j++){
            int st = j & 3;
            online_lse(v[j].x - r[j], m[st].x, s[st].x);
            online_lse(v[j].y - r[j], m[st].y, s[st].y);
            online_lse(v[j].z - r[j], m[st].z, s[st].z);
            online_lse(v[j].w - r[j], m[st].w, s[st].w);
        }
    }
    float4 M = m[0], S = s[0];
    #pragma unroll
    for (int j=1;j<4;j++){
        merge_lse(M.x, S.x, m[j].x, s[j].x);
        merge_lse(M.y, S.y, m[j].y, s[j].y);
        merge_lse(M.z, S.z, m[j].z, s[j].z);
        merge_lse(M.w, S.w, m[j].w, s[j].w);
    }
    __shared__ float4 sm16[16][16], ss16[16][16];
    sm16[rg][cg] = M; ss16[rg][cg] = S;
    __syncthreads();
    if (rg == 0){
        #pragma unroll
        for (int g=1; g<16; g++){
            float4 mg = sm16[g][cg], sg = ss16[g][cg];
            merge_lse(M.x, S.x, mg.x, sg.x);
            merge_lse(M.y, S.y, mg.y, sg.y);
            merge_lse(M.z, S.z, mg.z, sg.z);
            merge_lse(M.w, S.w, mg.w, sg.w);
        }
        int j = b*NNODE + chunk*64 + cg*4;
        d_Cv[j+0] = M.x + __logf(S.x);
        d_Cv[j+1] = M.y + __logf(S.y);
        d_Cv[j+2] = M.z + __logf(S.z);
        d_Cv[j+3] = M.w + __logf(S.w);
    }
}

__global__ void k_col_T(const float* __restrict__ Z){
    int b     = blockIdx.x >> 4;
    int chunk = blockIdx.x & 15;
    int cg    = threadIdx.x & 15;
    int rg    = threadIdx.x >> 4;
    __shared__ float rs[NNODE];
    for (int k=threadIdx.x; k<NNODE; k+=256) rs[k] = d_Rv[b*NNODE + k];
    __syncthreads();
    float4 cj = *((const float4*)(d_Cv + b*NNODE) + chunk*16 + cg);
    const float4* z = (const float4*)(Z + (size_t)b*NNODE*NNODE) + chunk*16 + cg;
    float4 s = {0.f,0.f,0.f,0.f};
    int i0 = rg*64;
    for (int i=i0; i<i0+64; i+=8){
        float4 v[8]; float r[8];
        #pragma unroll
        for (int j=0;j<8;j++){ v[j] = z[(size_t)(i+j)*256]; r[j] = rs[i+j]; }
        #pragma unroll
        for (int j=0;j<8;j++){
            s.x += __expf(v[j].x - r[j] - cj.x);
            s.y += __expf(v[j].y - r[j] - cj.y);
            s.z += __expf(v[j].z - r[j] - cj.z);
            s.w += __expf(v[j].w - r[j] - cj.w);
        }
    }
    __shared__ float4 ss16[16][16];
    ss16[rg][cg] = s;
    __syncthreads();
    if (rg == 0){
        #pragma unroll
        for (int g=1; g<16; g++){
            float4 sg = ss16[g][cg];
            s.x += sg.x; s.y += sg.y; s.z += sg.z; s.w += sg.w;
        }
        int j = b*NNODE + chunk*64 + cg*4;
        d_Tv[j+0]=s.x; d_Tv[j+1]=s.y; d_Tv[j+2]=s.z; d_Tv[j+3]=s.w;
    }
}

__global__ void k_final(const float* __restrict__ Z, float* __restrict__ P){
    size_t t = (size_t)blockIdx.x*256 + threadIdx.x;
    int row = (int)(t >> 10);
    int b   = row >> 10;
    int j   = (int)(t & 1023);
    P[t] = __expf(Z[t] - d_Rv[row] - d_Cv[b*NNODE + j]) / d_Tv[b*NNODE + j];
}

extern "C" void kernel_launch(void* const* d_in, const int* in_sizes, int n_in,
                              void* d_out, int out_size) {
    const float* X      = (const float*)d_in[0];
    const float* adj    = (const float*)d_in[1];
    const float* w_in   = (const float*)d_in[2];
    const float* b_in   = (const float*)d_in[3];
    const float* cw1    = (const float*)d_in[4];
    const float* cb1    = (const float*)d_in[5];
    const float* cw2    = (const float*)d_in[6];
    const float* cb2    = (const float*)d_in[7];
    const float* ca     = (const float*)d_in[8];
    const float* m1w    = (const float*)d_in[9];
    const float* m1b    = (const float*)d_in[10];
    const float* m2w    = (const float*)d_in[11];
    const float* m2b    = (const float*)d_in[12];
    float* Pout = (float*)d_out;
    float* Z0   = Pout + (size_t)TOTEL;

    float *hid, *hs, *g, *u1, *u2, *u3, *u4, *hp, *mid, *lg;
    cudaGetSymbolAddress((void**)&hid, d_hid);
    cudaGetSymbolAddress((void**)&hs,  d_hs);
    cudaGetSymbolAddress((void**)&g,   d_g);
    cudaGetSymbolAddress((void**)&u1,  d_u1);
    cudaGetSymbolAddress((void**)&u2,  d_u2);
    cudaGetSymbolAddress((void**)&u3,  d_u3);
    cudaGetSymbolAddress((void**)&u4,  d_u4);
    cudaGetSymbolAddress((void**)&hp,  d_hp);
    cudaGetSymbolAddress((void**)&mid, d_mid);
    cudaGetSymbolAddress((void**)&lg,  d_logits);
    float *dis, *invdeg;
    cudaGetSymbolAddress((void**)&dis,    d_dis);
    cudaGetSymbolAddress((void**)&invdeg, d_invdeg);

    cudaFuncSetAttribute(k_mma, cudaFuncAttributeMaxDynamicSharedMemorySize, SMTOT);
    cudaFuncSetAttribute(k_mma_dual, cudaFuncAttributeMaxDynamicSharedMemorySize, SMTOT);

    k_adj_stats<<<NROWS/8, 256>>>(adj);
    k_splitA<<<TOTEL/256, 256>>>(adj);

    // h0 = X @ w_in^T + b_in
    k_gemm_nt<<<dim3(2,128), 256>>>(X, 128, w_in, 128, b_in, hid, 768, 0);

    dim3 tg(2, 8, 16);
    dim3 tgd(4, 8, 16);
    for (int l = 0; l < 2; l++){
        int off  = 256*l;
        int offn = 256*(l+1);
        k_scale_hs<<<NROWS*HD/256, 256>>>(off);
        k_mma_dual<<<tgd, 256, SMTOT>>>(hs, g, dis, hid+off, 768, u1, invdeg);
        k_mma<<<tg, 256, SMTOT>>>(u1, 256, u2, 2, u1, 256, invdeg);
        k_mma<<<tg, 256, SMTOT>>>(u2, 256, u3, 2, u2, 256, invdeg);
        k_mma<<<tg, 256, SMTOT>>>(u3, 256, u4, 2, u3, 256, invdeg);
        k_attn<<<NROWS, 256>>>(off, ca + l*512);
        k_gemm_nt<<<dim3(2,128), 256>>>(hp,  256, cw1 + l*65536, 256, cb1 + l*256, mid, 256, 1);
        k_gemm_nt<<<dim3(2,128), 256>>>(mid, 256, cw2 + l*65536, 256, cb2 + l*256, hid + offn, 768, 1);
    }

    // mlp1 + mlp2
    k_gemm_nt<<<dim3(2,128), 256>>>(hid, 768, m1w, 768, m1b, mid, 256, 1);
    k_gemm_nt<<<dim3(8,128), 256>>>(mid, 256, m2w, 256, m2b, lg, 1024, 2);

    // Z0 = (logits + gumbel)/tau  (gsinit output)
    k_z0<<<TOTEL/256, 256>>>(Z0);

    // Sinkhorn: rank-1 log-domain state (R, C)
    k_zeroC<<<NROWS/256, 256>>>();
    for (int it = 0; it < 20; it++){
        k_row_lse<<<NROWS/8, 256>>>(Z0);
        k_col_lse<<<256, 256>>>(Z0);
    }
    k_row_lse<<<NROWS/8, 256>>>(Z0);
    k_col_T  <<<256, 256>>>(Z0);
    k_final  <<<TOTEL/256, 256>>>(Z0, Pout);
}

// round 16
// speedup vs baseline: 1.2716x; 1.1384x over previous
#include <cuda_runtime.h>
#include <cuda_bf16.h>
#include <cstdint>
#include <math.h>

#define NBATCH 16
#define NNODE  1024
#define HD     256
#define NROWS  (NBATCH*NNODE)
#define TOTEL  16777216

__device__ float d_hid[NROWS*768];
__device__ float d_hs [NROWS*HD];
__device__ float d_g  [NROWS*HD];
__device__ float d_u1 [NROWS*HD];
__device__ float d_u2 [NROWS*HD];
__device__ float d_u3 [NROWS*HD];
__device__ float d_u4 [NROWS*HD];
__device__ float d_hp [NROWS*HD];
__device__ float d_mid[NROWS*HD];
__device__ float d_logits[TOTEL];
__device__ float d_dis[NROWS];
__device__ float d_invdeg[NROWS];
__device__ float d_Rv[NROWS];
__device__ float d_Cv[NROWS];
__device__ float d_Tv[NROWS];

__device__ __forceinline__ float leakyf(float x){ return x > 0.f ? x : 0.01f*x; }

__global__ void k_adj_stats(const float* __restrict__ adj){
    int row  = blockIdx.x*8 + (threadIdx.x>>5);
    int lane = threadIdx.x & 31;
    const float* a = adj + (size_t)row*NNODE;
    float s = 0.f;
    #pragma unroll
    for (int k=0;k<32;k++) s += a[lane + 32*k];
    #pragma unroll
    for (int o=16;o;o>>=1) s += __shfl_xor_sync(0xffffffffu, s, o);
    if (lane==0){ d_dis[row] = rsqrtf(s + 1.f); d_invdeg[row] = 1.f/s; }
}

__global__ void k_scale_hs(int off){
    int idx = blockIdx.x*256 + threadIdx.x;
    int row = idx >> 8, col = idx & 255;
    d_hs[idx] = d_dis[row] * d_hid[(size_t)row*768 + off + col];
}

// ---------------- 3xTF32 mma.sync helpers (R13 winning config) ----------------
__device__ __forceinline__ void split_tf32(float v, uint32_t& hi, uint32_t& lo){
    uint32_t h;
    asm("cvt.rna.tf32.f32 %0, %1;" : "=r"(h) : "f"(v));
    float r = v - __uint_as_float(h);
    uint32_t l;
    asm("cvt.rna.tf32.f32 %0, %1;" : "=r"(l) : "f"(r));
    hi = h; lo = l;
}
__device__ __forceinline__ void mma_tf32(float* c,
    uint32_t a0, uint32_t a1, uint32_t a2, uint32_t a3,
    uint32_t b0, uint32_t b1){
    asm volatile(
        "mma.sync.aligned.m16n8k8.row.col.f32.tf32.tf32.f32 "
        "{%0,%1,%2,%3}, {%4,%5,%6,%7}, {%8,%9}, {%0,%1,%2,%3};"
        : "+f"(c[0]), "+f"(c[1]), "+f"(c[2]), "+f"(c[3])
        : "r"(a0), "r"(a1), "r"(a2), "r"(a3), "r"(b0), "r"(b1));
}

#define PAD 132

// ---- R13 mainloop body, verbatim, as macro (As/Bs static shared, declared by caller) ----
#define MMA13_MAINLOOP(APTR, BPTR, LDB)                                                      \
    {                                                                                        \
        float4 a0 = *(const float4*)(APTR);                                                  \
        float4 a1 = *(const float4*)(APTR + 4);                                              \
        float4 b0 = *(const float4*)(BPTR);                                                  \
        float4 b1 = *(const float4*)(BPTR + 4);                                              \
        As[0][acol+0][arow]=a0.x; As[0][acol+1][arow]=a0.y; As[0][acol+2][arow]=a0.z; As[0][acol+3][arow]=a0.w; \
        As[0][acol+4][arow]=a1.x; As[0][acol+5][arow]=a1.y; As[0][acol+6][arow]=a1.z; As[0][acol+7][arow]=a1.w; \
        *(float4*)&Bs[0][brow][bcol]   = b0;                                                 \
        *(float4*)&Bs[0][brow][bcol+4] = b1;                                                 \
    }                                                                                        \
    __syncthreads();                                                                         \
    const int ntile = NNODE/16;                                                              \
    for (int t = 0; t < ntile; t++){                                                         \
        int cur = t & 1;                                                                     \
        float4 pa0, pa1, pb0, pb1;                                                           \
        if (t+1 < ntile){                                                                    \
            pa0 = *(const float4*)((APTR) + (t+1)*16);                                       \
            pa1 = *(const float4*)((APTR) + (t+1)*16 + 4);                                   \
            pb0 = *(const float4*)((BPTR) + (size_t)(t+1)*16*(LDB));                         \
            pb1 = *(const float4*)((BPTR) + (size_t)(t+1)*16*(LDB) + 4);                     \
        }                                                                                    \
        _Pragma("unroll")                                                                    \
        for (int k8 = 0; k8 < 16; k8 += 8){                                                  \
            uint32_t ahi[2][4], alo[2][4];                                                   \
            _Pragma("unroll")                                                                \
            for (int f = 0; f < 2; f++){                                                     \
                int mb = wm + f*16 + lr;                                                     \
                float v0 = As[cur][k8+lc][mb];                                               \
                float v1 = As[cur][k8+lc][mb+8];                                             \
                float v2 = As[cur][k8+lc+4][mb];                                             \
                float v3 = As[cur][k8+lc+4][mb+8];                                           \
                split_tf32(v0, ahi[f][0], alo[f][0]);                                        \
                split_tf32(v1, ahi[f][1], alo[f][1]);                                        \
                split_tf32(v2, ahi[f][2], alo[f][2]);                                        \
                split_tf32(v3, ahi[f][3], alo[f][3]);                                        \
            }                                                                                \
            _Pragma("unroll")                                                                \
            for (int gh = 0; gh < 2; gh++){                                                  \
                uint32_t bhi[4][2], blo[4][2];                                               \
                _Pragma("unroll")                                                            \
                for (int g = 0; g < 4; g++){                                                 \
                    int n = wn + gh*32 + g*8 + lr;                                           \
                    split_tf32(Bs[cur][k8+lc][n],   bhi[g][0], blo[g][0]);                   \
                    split_tf32(Bs[cur][k8+lc+4][n], bhi[g][1], blo[g][1]);                   \
                }                                                                            \
                _Pragma("unroll")                                                            \
                for (int f = 0; f < 2; f++)                                                  \
                _Pragma("unroll")                                                            \
                for (int g = 0; g < 4; g++){                                                 \
                    float* c = acc[f][gh*4+g];                                               \
                    mma_tf32(c, ahi[f][0],ahi[f][1],ahi[f][2],ahi[f][3], bhi[g][0],bhi[g][1]); \
                    mma_tf32(c, ahi[f][0],ahi[f][1],ahi[f][2],ahi[f][3], blo[g][0],blo[g][1]); \
                    mma_tf32(c, alo[f][0],alo[f][1],alo[f][2],alo[f][3], bhi[g][0],bhi[g][1]); \
                }                                                                            \
            }                                                                                \
        }                                                                                    \
        if (t+1 < ntile){                                                                    \
            int nxt = cur ^ 1;                                                               \
            As[nxt][acol+0][arow]=pa0.x; As[nxt][acol+1][arow]=pa0.y; As[nxt][acol+2][arow]=pa0.z; As[nxt][acol+3][arow]=pa0.w; \
            As[nxt][acol+4][arow]=pa1.x; As[nxt][acol+5][arow]=pa1.y; As[nxt][acol+6][arow]=pa1.z; As[nxt][acol+7][arow]=pa1.w; \
            *(float4*)&Bs[nxt][brow][bcol]   = pb0;                                          \
            *(float4*)&Bs[nxt][brow][bcol+4] = pb1;                                          \
            __syncthreads();                                                                 \
        }                                                                                    \
    }

#define MMA13_EPILOGUE(MODE, AUX, LDAUX, VEC, OUT)                                           \
    _Pragma("unroll")                                                                        \
    for (int f = 0; f < 2; f++){                                                             \
        int r0 = m0 + wm + f*16 + lr;                                                        \
        size_t gi0 = (size_t)(bb*NNODE + r0);                                                \
        size_t gi1 = gi0 + 8;                                                                \
        float dv0 = (VEC)[gi0], dv1 = (VEC)[gi1];                                            \
        const float* aux0 = (AUX) + gi0*(size_t)(LDAUX) + n0 + wn;                           \
        const float* aux1 = (AUX) + gi1*(size_t)(LDAUX) + n0 + wn;                           \
        float* out0 = (OUT) + gi0*(size_t)256 + n0 + wn;                                     \
        float* out1 = (OUT) + gi1*(size_t)256 + n0 + wn;                                     \
        _Pragma("unroll")                                                                    \
        for (int g = 0; g < 8; g++){                                                         \
            int c = g*8 + lc*2;                                                              \
            float2 ax0 = *(const float2*)(aux0 + c);                                         \
            float2 ax1 = *(const float2*)(aux1 + c);                                         \
            float* a = acc[f][g];                                                            \
            float2 o0, o1;                                                                   \
            if ((MODE) == 1){                                                                \
                o0.x = leakyf(dv0*(a[0]+ax0.x)); o0.y = leakyf(dv0*(a[1]+ax0.y));            \
                o1.x = leakyf(dv1*(a[2]+ax1.x)); o1.y = leakyf(dv1*(a[3]+ax1.y));            \
            } else {                                                                         \
                o0.x = 0.5f*(ax0.x + a[0]*dv0); o0.y = 0.5f*(ax0.y + a[1]*dv0);              \
                o1.x = 0.5f*(ax1.x + a[2]*dv1); o1.y = 0.5f*(ax1.y + a[3]*dv1);              \
            }                                                                                \
            *(float2*)(out0 + c) = o0;                                                       \
            *(float2*)(out1 + c) = o1;                                                       \
        }                                                                                    \
    }

// batched adj GEMM on tensor cores (3xTF32, R13 winner)
__global__ __launch_bounds__(256,2) void k_mma(
    const float* __restrict__ Aadj, const float* __restrict__ B, int ldb,
    float* __restrict__ Cc, int mode,
    const float* __restrict__ aux, int ldaux, const float* __restrict__ vec)
{
    int bb = blockIdx.z;
    int n0 = blockIdx.x * 128;
    int m0 = blockIdx.y * 128;
    const float* Ab = Aadj + (size_t)bb*NNODE*NNODE;
    __shared__ float As[2][16][PAD];
    __shared__ float Bs[2][16][PAD];
    int tid  = threadIdx.x;
    int wid  = tid >> 5, lane = tid & 31;
    int lr = lane >> 2, lc = lane & 3;
    int wm = (wid & 3) * 32;
    int wn = (wid >> 2) * 64;
    int arow = tid >> 1, acol = (tid & 1)*8;
    int brow = tid >> 4, bcol = (tid & 15)*8;

    const float* aptr = Ab + (size_t)(m0+arow)*NNODE + acol;
    const float* bptr = B + (size_t)(bb*NNODE + brow)*ldb + n0 + bcol;
    float acc[2][8][4] = {};
    MMA13_MAINLOOP(aptr, bptr, ldb)
    MMA13_EPILOGUE(mode, aux, ldaux, vec, Cc)
}

// fused: blockIdx.x 0-1 -> GCN (B1->C1, mode1), 2-3 -> lazy walk (B2->C2, mode2)
__global__ __launch_bounds__(256,2) void k_mma_dual(
    const float* __restrict__ Aadj,
    const float* __restrict__ B1, float* __restrict__ C1, const float* __restrict__ vec1,
    const float* __restrict__ B2, int ldb2, float* __restrict__ C2, const float* __restrict__ vec2)
{
    int bb = blockIdx.z;
    int half = blockIdx.x >> 1;
    int n0 = (blockIdx.x & 1) * 128;
    int m0 = blockIdx.y * 128;
    const float* Ab = Aadj + (size_t)bb*NNODE*NNODE;
    __shared__ float As[2][16][PAD];
    __shared__ float Bs[2][16][PAD];
    int tid  = threadIdx.x;
    int wid  = tid >> 5, lane = tid & 31;
    int lr = lane >> 2, lc = lane & 3;
    int wm = (wid & 3) * 32;
    int wn = (wid >> 2) * 64;
    int arow = tid >> 1, acol = (tid & 1)*8;
    int brow = tid >> 4, bcol = (tid & 15)*8;

    const float* B = half ? B2 : B1;
    int ldb        = half ? ldb2 : 256;
    const float* aptr = Ab + (size_t)(m0+arow)*NNODE + acol;
    const float* bptr = B + (size_t)(bb*NNODE + brow)*ldb + n0 + bcol;
    float acc[2][8][4] = {};
    MMA13_MAINLOOP(aptr, bptr, ldb)
    if (half == 0){
        MMA13_EPILOGUE(1, B1, 256, vec1, C1)
    } else {
        MMA13_EPILOGUE(2, B2, ldb2, vec2, C2)
    }
}

// dense NT GEMM (SIMT)
#define BM 128
#define BN 128
#define BK 16
__global__ __launch_bounds__(256,2) void k_gemm_nt(
    const float* __restrict__ A, int lda,
    const float* __restrict__ W, int K, const float* __restrict__ bias,
    float* __restrict__ Cc, int ldc, int act)
{
    int n0 = blockIdx.x * BN;
    int m0 = blockIdx.y * BM;
    __shared__ float As[2][BK][BM];
    __shared__ float Bs[2][BK][BN];
    int tid  = threadIdx.x;
    int arow = tid >> 1;
    int acol = (tid & 1) * 8;
    int ty = tid >> 4, tx = tid & 15;

    const float* aptr = A + (size_t)(m0+arow)*lda + acol;
    const float* wptr = W + (size_t)(n0+arow)*K   + acol;

    float4 a0 = *(const float4*)(aptr);
    float4 a1 = *(const float4*)(aptr + 4);
    float4 w0 = *(const float4*)(wptr);
    float4 w1 = *(const float4*)(wptr + 4);
    As[0][acol+0][arow]=a0.x; As[0][acol+1][arow]=a0.y; As[0][acol+2][arow]=a0.z; As[0][acol+3][arow]=a0.w;
    As[0][acol+4][arow]=a1.x; As[0][acol+5][arow]=a1.y; As[0][acol+6][arow]=a1.z; As[0][acol+7][arow]=a1.w;
    Bs[0][acol+0][arow]=w0.x; Bs[0][acol+1][arow]=w0.y; Bs[0][acol+2][arow]=w0.z; Bs[0][acol+3][arow]=w0.w;
    Bs[0][acol+4][arow]=w1.x; Bs[0][acol+5][arow]=w1.y; Bs[0][acol+6][arow]=w1.z; Bs[0][acol+7][arow]=w1.w;
    __syncthreads();

    float acc[8][8] = {};
    const int ntile = K/BK;
    for (int t = 0; t < ntile; t++){
        int cur = t & 1;
        if (t+1 < ntile){
            a0 = *(const float4*)(aptr + (t+1)*BK);
            a1 = *(const float4*)(aptr + (t+1)*BK + 4);
            w0 = *(const float4*)(wptr + (t+1)*BK);
            w1 = *(const float4*)(wptr + (t+1)*BK + 4);
        }
        #pragma unroll
        for (int k=0;k<BK;k++){
            float4 fa0 = *(const float4*)&As[cur][k][ty*4];
            float4 fa1 = *(const float4*)&As[cur][k][64+ty*4];
            float4 fb0 = *(const float4*)&Bs[cur][k][tx*4];
            float4 fb1 = *(const float4*)&Bs[cur][k][64+tx*4];
            float ar[8] = {fa0.x,fa0.y,fa0.z,fa0.w,fa1.x,fa1.y,fa1.z,fa1.w};
            float br[8] = {fb0.x,fb0.y,fb0.z,fb0.w,fb1.x,fb1.y,fb1.z,fb1.w};
            #pragma unroll
            for (int m=0;m<8;m++)
                #pragma unroll
                for (int n=0;n<8;n++)
                    acc[m][n] = fmaf(ar[m], br[n], acc[m][n]);
        }
        if (t+1 < ntile){
            int nxt = cur ^ 1;
            As[nxt][acol+0][arow]=a0.x; As[nxt][acol+1][arow]=a0.y; As[nxt][acol+2][arow]=a0.z; As[nxt][acol+3][arow]=a0.w;
            As[nxt][acol+4][arow]=a1.x; As[nxt][acol+5][arow]=a1.y; As[nxt][acol+6][arow]=a1.z; As[nxt][acol+7][arow]=a1.w;
            Bs[nxt][acol+0][arow]=w0.x; Bs[nxt][acol+1][arow]=w0.y; Bs[nxt][acol+2][arow]=w0.z; Bs[nxt][acol+3][arow]=w0.w;
            Bs[nxt][acol+4][arow]=w1.x; Bs[nxt][acol+5][arow]=w1.y; Bs[nxt][acol+6][arow]=w1.z; Bs[nxt][acol+7][arow]=w1.w;
            __syncthreads();
        }
    }
    #pragma unroll
    for (int mh=0; mh<2; mh++)
    #pragma unroll
    for (int mi=0; mi<4; mi++){
        int m = mh*4+mi;
        size_t gi = (size_t)(m0 + mh*64 + ty*4 + mi);
        float* outr = Cc + gi*(size_t)ldc + n0;
        #pragma unroll
        for (int nh=0; nh<2; nh++){
            int colb = nh*64 + tx*4;
            float4 bs = *(const float4*)(bias + n0 + colb);
            float4 o;
            o.x = acc[m][nh*4+0] + bs.x;
            o.y = acc[m][nh*4+1] + bs.y;
            o.z = acc[m][nh*4+2] + bs.z;
            o.w = acc[m][nh*4+3] + bs.w;
            if (act == 1){
                o.x=leakyf(o.x); o.y=leakyf(o.y); o.z=leakyf(o.z); o.w=leakyf(o.w);
            } else if (act == 2){
                o.x=tanhf(o.x)*40.f; o.y=tanhf(o.y)*40.f; o.z=tanhf(o.z)*40.f; o.w=tanhf(o.w)*40.f;
            }
            *(float4*)(outr + colb) = o;
        }
    }
}

// channel attention + weighted mean over 4 channels
__global__ void k_attn(int off, const float* __restrict__ avec){
    int i = blockIdx.x, d = threadIdx.x;
    size_t b = (size_t)i*HD + d;
    float x  = d_hid[(size_t)i*768 + off + d];
    float c0 = d_g[b];
    float u1 = d_u1[b], u2 = d_u2[b], u4 = d_u4[b];
    float c1 = fabsf(x - u1), c2 = fabsf(u1 - u2), c3 = fabsf(u2 - u4);
    float ah = avec[256 + d];
    float e0 = fmaxf(c0, 0.f)*ah, e1 = c1*ah, e2 = c2*ah, e3 = c3*ah;
    #pragma unroll
    for (int o=16;o;o>>=1){
        e0 += __shfl_xor_sync(0xffffffffu, e0, o);
        e1 += __shfl_xor_sync(0xffffffffu, e1, o);
        e2 += __shfl_xor_sync(0xffffffffu, e2, o);
        e3 += __shfl_xor_sync(0xffffffffu, e3, o);
    }
    __shared__ float sred[4][8];
    __shared__ float tot[4];
    int w = d >> 5;
    if ((d & 31) == 0){ sred[0][w]=e0; sred[1][w]=e1; sred[2][w]=e2; sred[3][w]=e3; }
    __syncthreads();
    if (d < 4){
        float t = 0.f;
        #pragma unroll
        for (int ww=0; ww<8; ww++) t += sred[d][ww];
        tot[d] = t;
    }
    __syncthreads();
    float E0=tot[0], E1=tot[1], E2=tot[2], E3=tot[3];
    float m = fmaxf(fmaxf(E0,E1), fmaxf(E2,E3));
    float w0=__expf(E0-m), w1=__expf(E1-m), w2=__expf(E2-m), w3=__expf(E3-m);
    float inv = 0.25f / (w0+w1+w2+w3);
    d_hp[b] = inv * (w0*c0 + w1*c1 + w2*c2 + w3*c3);
}

// Threefry-2x32-20, key (0,42)
__device__ __forceinline__ void threefry(unsigned x0, unsigned x1, unsigned& o0, unsigned& o1){
    const unsigned ks0 = 0u, ks1 = 42u, ks2 = 0x1BD11BDAu ^ 42u;
    x0 += ks0; x1 += ks1;
#define TFR(r) { x0 += x1; x1 = (x1<<(r))|(x1>>(32-(r))); x1 ^= x0; }
    TFR(13) TFR(15) TFR(26) TFR(6)   x0+=ks1; x1+=ks2+1u;
    TFR(17) TFR(29) TFR(16) TFR(24)  x0+=ks2; x1+=ks0+2u;
    TFR(13) TFR(15) TFR(26) TFR(6)   x0+=ks0; x1+=ks1+3u;
    TFR(17) TFR(29) TFR(16) TFR(24)  x0+=ks1; x1+=ks2+4u;
    TFR(13) TFR(15) TFR(26) TFR(6)   x0+=ks2; x1+=ks0+5u;
#undef TFR
    o0 = x0; o1 = x1;
}

__device__ __forceinline__ float gumb(unsigned bits){
    float u = __uint_as_float((bits >> 9) | 0x3F800000u) - 1.0f;
    return -logf(-logf(u + 1e-20f) + 1e-20f) * 0.05f;
}

__global__ void k_z0(float* __restrict__ z0){
    unsigned t = blockIdx.x*256u + threadIdx.x;
    unsigned o0, o1;
    threefry(0u, t, o0, o1);
    z0[t] = (d_logits[t] + gumb(o0 ^ o1)) * 10.0f;
}

__global__ void k_zeroC(){ d_Cv[blockIdx.x*256 + threadIdx.x] = 0.f; }

__global__ void k_row_lse(const float* __restrict__ Z){
    int row  = blockIdx.x*8 + (threadIdx.x>>5);
    int lane = threadIdx.x & 31;
    int b    = row >> 10;
    const float* z = Z + (size_t)row*NNODE;
    const float* c = d_Cv + b*NNODE;
    float v[32];
    float m = -3.4e38f;
    #pragma unroll
    for (int k=0;k<32;k++){ v[k] = z[lane + 32*k] - c[lane + 32*k]; m = fmaxf(m, v[k]); }
    #pragma unroll
    for (int o=16;o;o>>=1) m = fmaxf(m, __shfl_xor_sync(0xffffffffu, m, o));
    float s = 0.f;
    #pragma unroll
    for (int k=0;k<32;k++) s += __expf(v[k] - m);
    #pragma unroll
    for (int o=16;o;o>>=1) s += __shfl_xor_sync(0xffffffffu, s, o);
    if (lane==0) d_Rv[row] = m + __logf(s);
}

__device__ __forceinline__ void online_lse(float v, float& m, float& s){
    if (v > m){ s = s*__expf(m - v) + 1.f; m = v; }
    else      { s += __expf(v - m); }
}
__device__ __forceinline__ void merge_lse(float& M, float& S, float mg, float sg){
    if (mg > M){ S = S*__expf(M - mg) + sg; M = mg; }
    else       { S += sg*__expf(mg - M); }
}

__global__ void k_col_lse(const float* __restrict__ Z){
    int b     = blockIdx.x >> 4;
    int chunk = blockIdx.x & 15;
    int cg    = threadIdx.x & 15;
    int rg    = threadIdx.x >> 4;
    __shared__ float rs[NNODE];
    for (int k=threadIdx.x; k<NNODE; k+=256) rs[k] = d_Rv[b*NNODE + k];
    __syncthreads();
    const float4* z = (const float4*)(Z + (size_t)b*NNODE*NNODE) + chunk*16 + cg;
    float4 m[4], s[4];
    #pragma unroll
    for (int j=0;j<4;j++){
        m[j] = make_float4(-3.4e38f,-3.4e38f,-3.4e38f,-3.4e38f);
        s[j] = make_float4(0.f,0.f,0.f,0.f);
    }
    int i0 = rg*64;
    for (int i=i0; i<i0+64; i+=8){
        float4 v[8]; float r[8];
        #pragma unroll
        for (int j=0;j<8;j++){ v[j] = z[(size_t)(i+j)*256]; r[j] = rs[i+j]; }
        #pragma unroll
        for (int j=0;j<8;j++){
            int st = j & 3;
            online_lse(v[j].x - r[j], m[st].x, s[st].x);
            online_lse(v[j].y - r[j], m[st].y, s[st].y);
            online_lse(v[j].z - r[j], m[st].z, s[st].z);
            online_lse(v[j].w - r[j], m[st].w, s[st].w);
        }
    }
    float4 M = m[0], S = s[0];
    #pragma unroll
    for (int j=1;j<4;j++){
        merge_lse(M.x, S.x, m[j].x, s[j].x);
        merge_lse(M.y, S.y, m[j].y, s[j].y);
        merge_lse(M.z, S.z, m[j].z, s[j].z);
        merge_lse(M.w, S.w, m[j].w, s[j].w);
    }
    __shared__ float4 sm16[16][16], ss16[16][16];
    sm16[rg][cg] = M; ss16[rg][cg] = S;
    __syncthreads();
    if (rg == 0){
        #pragma unroll
        for (int g=1; g<16; g++){
            float4 mg = sm16[g][cg], sg = ss16[g][cg];
            merge_lse(M.x, S.x, mg.x, sg.x);
            merge_lse(M.y, S.y, mg.y, sg.y);
            merge_lse(M.z, S.z, mg.z, sg.z);
            merge_lse(M.w, S.w, mg.w, sg.w);
        }
        int j = b*NNODE + chunk*64 + cg*4;
        d_Cv[j+0] = M.x + __logf(S.x);
        d_Cv[j+1] = M.y + __logf(S.y);
        d_Cv[j+2] = M.z + __logf(S.z);
        d_Cv[j+3] = M.w + __logf(S.w);
    }
}

__global__ void k_col_T(const float* __restrict__ Z){
    int b     = blockIdx.x >> 4;
    int chunk = blockIdx.x & 15;
    int cg    = threadIdx.x & 15;
    int rg    = threadIdx.x >> 4;
    __shared__ float rs[NNODE];
    for (int k=threadIdx.x; k<NNODE; k+=256) rs[k] = d_Rv[b*NNODE + k];
    __syncthreads();
    float4 cj = *((const float4*)(d_Cv + b*NNODE) + chunk*16 + cg);
    const float4* z = (const float4*)(Z + (size_t)b*NNODE*NNODE) + chunk*16 + cg;
    float4 s = {0.f,0.f,0.f,0.f};
    int i0 = rg*64;
    for (int i=i0; i<i0+64; i+=8){
        float4 v[8]; float r[8];
        #pragma unroll
        for (int j=0;j<8;j++){ v[j] = z[(size_t)(i+j)*256]; r[j] = rs[i+j]; }
        #pragma unroll
        for (int j=0;j<8;j++){
            s.x += __expf(v[j].x - r[j] - cj.x);
            s.y += __expf(v[j].y - r[j] - cj.y);
            s.z += __expf(v[j].z - r[j] - cj.z);
            s.w += __expf(v[j].w - r[j] - cj.w);
        }
    }
    __shared__ float4 ss16[16][16];
    ss16[rg][cg] = s;
    __syncthreads();
    if (rg == 0){
        #pragma unroll
        for (int g=1; g<16; g++){
            float4 sg = ss16[g][cg];
            s.x += sg.x; s.y += sg.y; s.z += sg.z; s.w += sg.w;
        }
        int j = b*NNODE + chunk*64 + cg*4;
        d_Tv[j+0]=s.x; d_Tv[j+1]=s.y; d_Tv[j+2]=s.z; d_Tv[j+3]=s.w;
    }
}

__global__ void k_final(const float* __restrict__ Z, float* __restrict__ P){
    size_t t = (size_t)blockIdx.x*256 + threadIdx.x;
    int row = (int)(t >> 10);
    int b   = row >> 10;
    int j   = (int)(t & 1023);
    P[t] = __expf(Z[t] - d_Rv[row] - d_Cv[b*NNODE + j]) / d_Tv[b*NNODE + j];
}

extern "C" void kernel_launch(void* const* d_in, const int* in_sizes, int n_in,
                              void* d_out, int out_size) {
    const float* X      = (const float*)d_in[0];
    const float* adj    = (const float*)d_in[1];
    const float* w_in   = (const float*)d_in[2];
    const float* b_in   = (const float*)d_in[3];
    const float* cw1    = (const float*)d_in[4];
    const float* cb1    = (const float*)d_in[5];
    const float* cw2    = (const float*)d_in[6];
    const float* cb2    = (const float*)d_in[7];
    const float* ca     = (const float*)d_in[8];
    const float* m1w    = (const float*)d_in[9];
    const float* m1b    = (const float*)d_in[10];
    const float* m2w    = (const float*)d_in[11];
    const float* m2b    = (const float*)d_in[12];
    float* Pout = (float*)d_out;
    float* Z0   = Pout + (size_t)TOTEL;

    float *hid, *hs, *g, *u1, *u2, *u3, *u4, *hp, *mid, *lg;
    cudaGetSymbolAddress((void**)&hid, d_hid);
    cudaGetSymbolAddress((void**)&hs,  d_hs);
    cudaGetSymbolAddress((void**)&g,   d_g);
    cudaGetSymbolAddress((void**)&u1,  d_u1);
    cudaGetSymbolAddress((void**)&u2,  d_u2);
    cudaGetSymbolAddress((void**)&u3,  d_u3);
    cudaGetSymbolAddress((void**)&u4,  d_u4);
    cudaGetSymbolAddress((void**)&hp,  d_hp);
    cudaGetSymbolAddress((void**)&mid, d_mid);
    cudaGetSymbolAddress((void**)&lg,  d_logits);
    float *dis, *invdeg;
    cudaGetSymbolAddress((void**)&dis,    d_dis);
    cudaGetSymbolAddress((void**)&invdeg, d_invdeg);

    k_adj_stats<<<NROWS/8, 256>>>(adj);

    // h0 = X @ w_in^T + b_in
    k_gemm_nt<<<dim3(2,128), 256>>>(X, 128, w_in, 128, b_in, hid, 768, 0);

    dim3 tg(2, 8, 16);
    dim3 tgd(4, 8, 16);
    for (int l = 0; l < 2; l++){
        int off  = 256*l;
        int offn = 256*(l+1);
        k_scale_hs<<<NROWS*HD/256, 256>>>(off);
        k_mma_dual<<<tgd, 256>>>(adj, hs, g, dis, hid+off, 768, u1, invdeg);
        k_mma<<<tg, 256>>>(adj, u1, 256, u2, 2, u1, 256, invdeg);
        k_mma<<<tg, 256>>>(adj, u2, 256, u3, 2, u2, 256, invdeg);
        k_mma<<<tg, 256>>>(adj, u3, 256, u4, 2, u3, 256, invdeg);
        k_attn<<<NROWS, 256>>>(off, ca + l*512);
        k_gemm_nt<<<dim3(2,128), 256>>>(hp,  256, cw1 + l*65536, 256, cb1 + l*256, mid, 256, 1);
        k_gemm_nt<<<dim3(2,128), 256>>>(mid, 256, cw2 + l*65536, 256, cb2 + l*256, hid + offn, 768, 1);
    }

    // mlp1 + mlp2
    k_gemm_nt<<<dim3(2,128), 256>>>(hid, 768, m1w, 768, m1b, mid, 256, 1);
    k_gemm_nt<<<dim3(8,128), 256>>>(mid, 256, m2w, 256, m2b, lg, 1024, 2);

    // Z0 = (logits + gumbel)/tau  (gsinit output)
    k_z0<<<TOTEL/256, 256>>>(Z0);

    // Sinkhorn: rank-1 log-domain state (R, C)
    k_zeroC<<<NROWS/256, 256>>>();
    for (int it = 0; it < 20; it++){
        k_row_lse<<<NROWS/8, 256>>>(Z0);
        k_col_lse<<<256, 256>>>(Z0);
    }
    k_row_lse<<<NROWS/8, 256>>>(Z0);
    k_col_T  <<<256, 256>>>(Z0);
    k_final  <<<TOTEL/256, 256>>>(Z0, Pout);
}

// round 17
// speedup vs baseline: 1.2938x; 1.0175x over previous
#include <cuda_runtime.h>
#include <cuda_bf16.h>
#include <cstdint>
#include <math.h>

#define NBATCH 16
#define NNODE  1024
#define HD     256
#define NROWS  (NBATCH*NNODE)
#define TOTEL  16777216

__device__ float d_hid[NROWS*768];
__device__ float d_hs [NROWS*HD];
__device__ float d_g  [NROWS*HD];
__device__ float d_u1 [NROWS*HD];
__device__ float d_u2 [NROWS*HD];
__device__ float d_u3 [NROWS*HD];
__device__ float d_u4 [NROWS*HD];
__device__ float d_hp [NROWS*HD];
__device__ float d_mid[NROWS*HD];
__device__ float d_logits[TOTEL];
__device__ float d_dis[NROWS];
__device__ float d_invdeg[NROWS];
__device__ float d_Rv[NROWS];
__device__ float d_Cv[NROWS];
__device__ float d_Tv[NROWS];

__device__ __forceinline__ float leakyf(float x){ return x > 0.f ? x : 0.01f*x; }

__global__ void k_adj_stats(const float* __restrict__ adj){
    int row  = blockIdx.x*8 + (threadIdx.x>>5);
    int lane = threadIdx.x & 31;
    const float* a = adj + (size_t)row*NNODE;
    float s = 0.f;
    #pragma unroll
    for (int k=0;k<32;k++) s += a[lane + 32*k];
    #pragma unroll
    for (int o=16;o;o>>=1) s += __shfl_xor_sync(0xffffffffu, s, o);
    if (lane==0){ d_dis[row] = rsqrtf(s + 1.f); d_invdeg[row] = 1.f/s; }
}

__global__ void k_scale_hs(int off){
    int idx = blockIdx.x*256 + threadIdx.x;
    int row = idx >> 8, col = idx & 255;
    d_hs[idx] = d_dis[row] * d_hid[(size_t)row*768 + off + col];
}

// ---------------- 3xTF32 mma.sync helpers (R13 winning config) ----------------
__device__ __forceinline__ void split_tf32(float v, uint32_t& hi, uint32_t& lo){
    uint32_t h;
    asm("cvt.rna.tf32.f32 %0, %1;" : "=r"(h) : "f"(v));
    float r = v - __uint_as_float(h);
    uint32_t l;
    asm("cvt.rna.tf32.f32 %0, %1;" : "=r"(l) : "f"(r));
    hi = h; lo = l;
}
__device__ __forceinline__ void mma_tf32(float* c,
    uint32_t a0, uint32_t a1, uint32_t a2, uint32_t a3,
    uint32_t b0, uint32_t b1){
    asm volatile(
        "mma.sync.aligned.m16n8k8.row.col.f32.tf32.tf32.f32 "
        "{%0,%1,%2,%3}, {%4,%5,%6,%7}, {%8,%9}, {%0,%1,%2,%3};"
        : "+f"(c[0]), "+f"(c[1]), "+f"(c[2]), "+f"(c[3])
        : "r"(a0), "r"(a1), "r"(a2), "r"(a3), "r"(b0), "r"(b1));
}

#define PAD 132

// ---- inner k8 loop (shared by all mma kernels); uses As,Bs,acc,wm,wn,lr,lc ----
#define MMA13_K8LOOP(CUR)                                                                    \
    _Pragma("unroll")                                                                        \
    for (int k8 = 0; k8 < 16; k8 += 8){                                                      \
        uint32_t ahi[2][4], alo[2][4];                                                       \
        _Pragma("unroll")                                                                    \
        for (int f = 0; f < 2; f++){                                                         \
            int mb = wm + f*16 + lr;                                                         \
            float v0 = As[CUR][k8+lc][mb];                                                   \
            float v1 = As[CUR][k8+lc][mb+8];                                                 \
            float v2 = As[CUR][k8+lc+4][mb];                                                 \
            float v3 = As[CUR][k8+lc+4][mb+8];                                               \
            split_tf32(v0, ahi[f][0], alo[f][0]);                                            \
            split_tf32(v1, ahi[f][1], alo[f][1]);                                            \
            split_tf32(v2, ahi[f][2], alo[f][2]);                                            \
            split_tf32(v3, ahi[f][3], alo[f][3]);                                            \
        }                                                                                    \
        _Pragma("unroll")                                                                    \
        for (int gh = 0; gh < 2; gh++){                                                      \
            uint32_t bhi[4][2], blo[4][2];                                                   \
            _Pragma("unroll")                                                                \
            for (int g = 0; g < 4; g++){                                                     \
                int n = wn + gh*32 + g*8 + lr;                                               \
                split_tf32(Bs[CUR][k8+lc][n],   bhi[g][0], blo[g][0]);                       \
                split_tf32(Bs[CUR][k8+lc+4][n], bhi[g][1], blo[g][1]);                       \
            }                                                                                \
            _Pragma("unroll")                                                                \
            for (int f = 0; f < 2; f++)                                                      \
            _Pragma("unroll")                                                                \
            for (int g = 0; g < 4; g++){                                                     \
                float* c = acc[f][gh*4+g];                                                   \
                mma_tf32(c, ahi[f][0],ahi[f][1],ahi[f][2],ahi[f][3], bhi[g][0],bhi[g][1]);   \
                mma_tf32(c, ahi[f][0],ahi[f][1],ahi[f][2],ahi[f][3], blo[g][0],blo[g][1]);   \
                mma_tf32(c, alo[f][0],alo[f][1],alo[f][2],alo[f][3], bhi[g][0],bhi[g][1]);   \
            }                                                                                \
        }                                                                                    \
    }

// ---- R13 mainloop body (adjacency form: B loaded K-row-wise) ----
#define MMA13_MAINLOOP(APTR, BPTR, LDB)                                                      \
    {                                                                                        \
        float4 a0 = *(const float4*)(APTR);                                                  \
        float4 a1 = *(const float4*)(APTR + 4);                                              \
        float4 b0 = *(const float4*)(BPTR);                                                  \
        float4 b1 = *(const float4*)(BPTR + 4);                                              \
        As[0][acol+0][arow]=a0.x; As[0][acol+1][arow]=a0.y; As[0][acol+2][arow]=a0.z; As[0][acol+3][arow]=a0.w; \
        As[0][acol+4][arow]=a1.x; As[0][acol+5][arow]=a1.y; As[0][acol+6][arow]=a1.z; As[0][acol+7][arow]=a1.w; \
        *(float4*)&Bs[0][brow][bcol]   = b0;                                                 \
        *(float4*)&Bs[0][brow][bcol+4] = b1;                                                 \
    }                                                                                        \
    __syncthreads();                                                                         \
    const int ntile = NNODE/16;                                                              \
    for (int t = 0; t < ntile; t++){                                                         \
        int cur = t & 1;                                                                     \
        float4 pa0, pa1, pb0, pb1;                                                           \
        if (t+1 < ntile){                                                                    \
            pa0 = *(const float4*)((APTR) + (t+1)*16);                                       \
            pa1 = *(const float4*)((APTR) + (t+1)*16 + 4);                                   \
            pb0 = *(const float4*)((BPTR) + (size_t)(t+1)*16*(LDB));                         \
            pb1 = *(const float4*)((BPTR) + (size_t)(t+1)*16*(LDB) + 4);                     \
        }                                                                                    \
        MMA13_K8LOOP(cur)                                                                    \
        if (t+1 < ntile){                                                                    \
            int nxt = cur ^ 1;                                                               \
            As[nxt][acol+0][arow]=pa0.x; As[nxt][acol+1][arow]=pa0.y; As[nxt][acol+2][arow]=pa0.z; As[nxt][acol+3][arow]=pa0.w; \
            As[nxt][acol+4][arow]=pa1.x; As[nxt][acol+5][arow]=pa1.y; As[nxt][acol+6][arow]=pa1.z; As[nxt][acol+7][arow]=pa1.w; \
            *(float4*)&Bs[nxt][brow][bcol]   = pb0;                                          \
            *(float4*)&Bs[nxt][brow][bcol+4] = pb1;                                          \
            __syncthreads();                                                                 \
        }                                                                                    \
    }

#define MMA13_EPILOGUE(MODE, AUX, LDAUX, VEC, OUT)                                           \
    _Pragma("unroll")                                                                        \
    for (int f = 0; f < 2; f++){                                                             \
        int r0 = m0 + wm + f*16 + lr;                                                        \
        size_t gi0 = (size_t)(bb*NNODE + r0);                                                \
        size_t gi1 = gi0 + 8;                                                                \
        float dv0 = (VEC)[gi0], dv1 = (VEC)[gi1];                                            \
        const float* aux0 = (AUX) + gi0*(size_t)(LDAUX) + n0 + wn;                           \
        const float* aux1 = (AUX) + gi1*(size_t)(LDAUX) + n0 + wn;                           \
        float* out0 = (OUT) + gi0*(size_t)256 + n0 + wn;                                     \
        float* out1 = (OUT) + gi1*(size_t)256 + n0 + wn;                                     \
        _Pragma("unroll")                                                                    \
        for (int g = 0; g < 8; g++){                                                         \
            int c = g*8 + lc*2;                                                              \
            float2 ax0 = *(const float2*)(aux0 + c);                                         \
            float2 ax1 = *(const float2*)(aux1 + c);                                         \
            float* a = acc[f][g];                                                            \
            float2 o0, o1;                                                                   \
            if ((MODE) == 1){                                                                \
                o0.x = leakyf(dv0*(a[0]+ax0.x)); o0.y = leakyf(dv0*(a[1]+ax0.y));            \
                o1.x = leakyf(dv1*(a[2]+ax1.x)); o1.y = leakyf(dv1*(a[3]+ax1.y));            \
            } else {                                                                         \
                o0.x = 0.5f*(ax0.x + a[0]*dv0); o0.y = 0.5f*(ax0.y + a[1]*dv0);              \
                o1.x = 0.5f*(ax1.x + a[2]*dv1); o1.y = 0.5f*(ax1.y + a[3]*dv1);              \
            }                                                                                \
            *(float2*)(out0 + c) = o0;                                                       \
            *(float2*)(out1 + c) = o1;                                                       \
        }                                                                                    \
    }

// batched adj GEMM on tensor cores (3xTF32, R13 winner)
__global__ __launch_bounds__(256,2) void k_mma(
    const float* __restrict__ Aadj, const float* __restrict__ B, int ldb,
    float* __restrict__ Cc, int mode,
    const float* __restrict__ aux, int ldaux, const float* __restrict__ vec)
{
    int bb = blockIdx.z;
    int n0 = blockIdx.x * 128;
    int m0 = blockIdx.y * 128;
    const float* Ab = Aadj + (size_t)bb*NNODE*NNODE;
    __shared__ float As[2][16][PAD];
    __shared__ float Bs[2][16][PAD];
    int tid  = threadIdx.x;
    int wid  = tid >> 5, lane = tid & 31;
    int lr = lane >> 2, lc = lane & 3;
    int wm = (wid & 3) * 32;
    int wn = (wid >> 2) * 64;
    int arow = tid >> 1, acol = (tid & 1)*8;
    int brow = tid >> 4, bcol = (tid & 15)*8;

    const float* aptr = Ab + (size_t)(m0+arow)*NNODE + acol;
    const float* bptr = B + (size_t)(bb*NNODE + brow)*ldb + n0 + bcol;
    float acc[2][8][4] = {};
    MMA13_MAINLOOP(aptr, bptr, ldb)
    MMA13_EPILOGUE(mode, aux, ldaux, vec, Cc)
}

// fused: blockIdx.x 0-1 -> GCN (B1->C1, mode1), 2-3 -> lazy walk (B2->C2, mode2)
__global__ __launch_bounds__(256,2) void k_mma_dual(
    const float* __restrict__ Aadj,
    const float* __restrict__ B1, float* __restrict__ C1, const float* __restrict__ vec1,
    const float* __restrict__ B2, int ldb2, float* __restrict__ C2, const float* __restrict__ vec2)
{
    int bb = blockIdx.z;
    int half = blockIdx.x >> 1;
    int n0 = (blockIdx.x & 1) * 128;
    int m0 = blockIdx.y * 128;
    const float* Ab = Aadj + (size_t)bb*NNODE*NNODE;
    __shared__ float As[2][16][PAD];
    __shared__ float Bs[2][16][PAD];
    int tid  = threadIdx.x;
    int wid  = tid >> 5, lane = tid & 31;
    int lr = lane >> 2, lc = lane & 3;
    int wm = (wid & 3) * 32;
    int wn = (wid >> 2) * 64;
    int arow = tid >> 1, acol = (tid & 1)*8;
    int brow = tid >> 4, bcol = (tid & 15)*8;

    const float* B = half ? B2 : B1;
    int ldb        = half ? ldb2 : 256;
    const float* aptr = Ab + (size_t)(m0+arow)*NNODE + acol;
    const float* bptr = B + (size_t)(bb*NNODE + brow)*ldb + n0 + bcol;
    float acc[2][8][4] = {};
    MMA13_MAINLOOP(aptr, bptr, ldb)
    if (half == 0){
        MMA13_EPILOGUE(1, B1, 256, vec1, C1)
    } else {
        MMA13_EPILOGUE(2, B2, ldb2, vec2, C2)
    }
}

// dense NT GEMM on tensor cores (3xTF32): C = act(A @ W^T + bias)
// A [M,lda] row-major, W [N,K] row-major; both loaded row-wise, scatter-transposed.
// act: 0 none, 1 leaky, 2 tanh*40
__global__ __launch_bounds__(256,2) void k_mma_nt(
    const float* __restrict__ A, int lda,
    const float* __restrict__ W, int K, const float* __restrict__ bias,
    float* __restrict__ Cc, int ldc, int act)
{
    int n0 = blockIdx.x * 128;
    int m0 = blockIdx.y * 128;
    __shared__ float As[2][16][PAD];
    __shared__ float Bs[2][16][PAD];
    int tid  = threadIdx.x;
    int wid  = tid >> 5, lane = tid & 31;
    int lr = lane >> 2, lc = lane & 3;
    int wm = (wid & 3) * 32;
    int wn = (wid >> 2) * 64;
    int arow = tid >> 1, acol = (tid & 1)*8;

    const float* aptr = A + (size_t)(m0+arow)*lda + acol;
    const float* wptr = W + (size_t)(n0+arow)*K   + acol;
    float acc[2][8][4] = {};
    {
        float4 a0 = *(const float4*)(aptr);
        float4 a1 = *(const float4*)(aptr + 4);
        float4 w0 = *(const float4*)(wptr);
        float4 w1 = *(const float4*)(wptr + 4);
        As[0][acol+0][arow]=a0.x; As[0][acol+1][arow]=a0.y; As[0][acol+2][arow]=a0.z; As[0][acol+3][arow]=a0.w;
        As[0][acol+4][arow]=a1.x; As[0][acol+5][arow]=a1.y; As[0][acol+6][arow]=a1.z; As[0][acol+7][arow]=a1.w;
        Bs[0][acol+0][arow]=w0.x; Bs[0][acol+1][arow]=w0.y; Bs[0][acol+2][arow]=w0.z; Bs[0][acol+3][arow]=w0.w;
        Bs[0][acol+4][arow]=w1.x; Bs[0][acol+5][arow]=w1.y; Bs[0][acol+6][arow]=w1.z; Bs[0][acol+7][arow]=w1.w;
    }
    __syncthreads();
    const int nt = K/16;
    for (int t = 0; t < nt; t++){
        int cur = t & 1;
        float4 pa0, pa1, pw0, pw1;
        if (t+1 < nt){
            pa0 = *(const float4*)(aptr + (t+1)*16);
            pa1 = *(const float4*)(aptr + (t+1)*16 + 4);
            pw0 = *(const float4*)(wptr + (t+1)*16);
            pw1 = *(const float4*)(wptr + (t+1)*16 + 4);
        }
        MMA13_K8LOOP(cur)
        if (t+1 < nt){
            int nxt = cur ^ 1;
            As[nxt][acol+0][arow]=pa0.x; As[nxt][acol+1][arow]=pa0.y; As[nxt][acol+2][arow]=pa0.z; As[nxt][acol+3][arow]=pa0.w;
            As[nxt][acol+4][arow]=pa1.x; As[nxt][acol+5][arow]=pa1.y; As[nxt][acol+6][arow]=pa1.z; As[nxt][acol+7][arow]=pa1.w;
            Bs[nxt][acol+0][arow]=pw0.x; Bs[nxt][acol+1][arow]=pw0.y; Bs[nxt][acol+2][arow]=pw0.z; Bs[nxt][acol+3][arow]=pw0.w;
            Bs[nxt][acol+4][arow]=pw1.x; Bs[nxt][acol+5][arow]=pw1.y; Bs[nxt][acol+6][arow]=pw1.z; Bs[nxt][acol+7][arow]=pw1.w;
            __syncthreads();
        }
    }
    #pragma unroll
    for (int f = 0; f < 2; f++){
        int r0 = m0 + wm + f*16 + lr;
        float* out0 = Cc + (size_t)r0*ldc + n0 + wn;
        float* out1 = Cc + (size_t)(r0+8)*ldc + n0 + wn;
        #pragma unroll
        for (int g = 0; g < 8; g++){
            int c = g*8 + lc*2;
            float2 bs2 = *(const float2*)(bias + n0 + wn + c);
            float* a = acc[f][g];
            float2 o0, o1;
            o0.x = a[0] + bs2.x; o0.y = a[1] + bs2.y;
            o1.x = a[2] + bs2.x; o1.y = a[3] + bs2.y;
            if (act == 1){
                o0.x=leakyf(o0.x); o0.y=leakyf(o0.y); o1.x=leakyf(o1.x); o1.y=leakyf(o1.y);
            } else if (act == 2){
                o0.x=tanhf(o0.x)*40.f; o0.y=tanhf(o0.y)*40.f;
                o1.x=tanhf(o1.x)*40.f; o1.y=tanhf(o1.y)*40.f;
            }
            *(float2*)(out0 + c) = o0;
            *(float2*)(out1 + c) = o1;
        }
    }
}

// channel attention + weighted mean over 4 channels
__global__ void k_attn(int off, const float* __restrict__ avec){
    int i = blockIdx.x, d = threadIdx.x;
    size_t b = (size_t)i*HD + d;
    float x  = d_hid[(size_t)i*768 + off + d];
    float c0 = d_g[b];
    float u1 = d_u1[b], u2 = d_u2[b], u4 = d_u4[b];
    float c1 = fabsf(x - u1), c2 = fabsf(u1 - u2), c3 = fabsf(u2 - u4);
    float ah = avec[256 + d];
    float e0 = fmaxf(c0, 0.f)*ah, e1 = c1*ah, e2 = c2*ah, e3 = c3*ah;
    #pragma unroll
    for (int o=16;o;o>>=1){
        e0 += __shfl_xor_sync(0xffffffffu, e0, o);
        e1 += __shfl_xor_sync(0xffffffffu, e1, o);
        e2 += __shfl_xor_sync(0xffffffffu, e2, o);
        e3 += __shfl_xor_sync(0xffffffffu, e3, o);
    }
    __shared__ float sred[4][8];
    __shared__ float tot[4];
    int w = d >> 5;
    if ((d & 31) == 0){ sred[0][w]=e0; sred[1][w]=e1; sred[2][w]=e2; sred[3][w]=e3; }
    __syncthreads();
    if (d < 4){
        float t = 0.f;
        #pragma unroll
        for (int ww=0; ww<8; ww++) t += sred[d][ww];
        tot[d] = t;
    }
    __syncthreads();
    float E0=tot[0], E1=tot[1], E2=tot[2], E3=tot[3];
    float m = fmaxf(fmaxf(E0,E1), fmaxf(E2,E3));
    float w0=__expf(E0-m), w1=__expf(E1-m), w2=__expf(E2-m), w3=__expf(E3-m);
    float inv = 0.25f / (w0+w1+w2+w3);
    d_hp[b] = inv * (w0*c0 + w1*c1 + w2*c2 + w3*c3);
}

// Threefry-2x32-20, key (0,42)
__device__ __forceinline__ void threefry(unsigned x0, unsigned x1, unsigned& o0, unsigned& o1){
    const unsigned ks0 = 0u, ks1 = 42u, ks2 = 0x1BD11BDAu ^ 42u;
    x0 += ks0; x1 += ks1;
#define TFR(r) { x0 += x1; x1 = (x1<<(r))|(x1>>(32-(r))); x1 ^= x0; }
    TFR(13) TFR(15) TFR(26) TFR(6)   x0+=ks1; x1+=ks2+1u;
    TFR(17) TFR(29) TFR(16) TFR(24)  x0+=ks2; x1+=ks0+2u;
    TFR(13) TFR(15) TFR(26) TFR(6)   x0+=ks0; x1+=ks1+3u;
    TFR(17) TFR(29) TFR(16) TFR(24)  x0+=ks1; x1+=ks2+4u;
    TFR(13) TFR(15) TFR(26) TFR(6)   x0+=ks2; x1+=ks0+5u;
#undef TFR
    o0 = x0; o1 = x1;
}

__device__ __forceinline__ float gumb(unsigned bits){
    float u = __uint_as_float((bits >> 9) | 0x3F800000u) - 1.0f;
    return -logf(-logf(u + 1e-20f) + 1e-20f) * 0.05f;
}

__global__ void k_z0(float* __restrict__ z0){
    unsigned t = blockIdx.x*256u + threadIdx.x;
    unsigned o0, o1;
    threefry(0u, t, o0, o1);
    z0[t] = (d_logits[t] + gumb(o0 ^ o1)) * 10.0f;
}

__global__ void k_zeroC(){ d_Cv[blockIdx.x*256 + threadIdx.x] = 0.f; }

__global__ void k_row_lse(const float* __restrict__ Z){
    int row  = blockIdx.x*8 + (threadIdx.x>>5);
    int lane = threadIdx.x & 31;
    int b    = row >> 10;
    const float* z = Z + (size_t)row*NNODE;
    const float* c = d_Cv + b*NNODE;
    float v[32];
    float m = -3.4e38f;
    #pragma unroll
    for (int k=0;k<32;k++){ v[k] = z[lane + 32*k] - c[lane + 32*k]; m = fmaxf(m, v[k]); }
    #pragma unroll
    for (int o=16;o;o>>=1) m = fmaxf(m, __shfl_xor_sync(0xffffffffu, m, o));
    float s = 0.f;
    #pragma unroll
    for (int k=0;k<32;k++) s += __expf(v[k] - m);
    #pragma unroll
    for (int o=16;o;o>>=1) s += __shfl_xor_sync(0xffffffffu, s, o);
    if (lane==0) d_Rv[row] = m + __logf(s);
}

__device__ __forceinline__ void online_lse(float v, float& m, float& s){
    if (v > m){ s = s*__expf(m - v) + 1.f; m = v; }
    else      { s += __expf(v - m); }
}
__device__ __forceinline__ void merge_lse(float& M, float& S, float mg, float sg){
    if (mg > M){ S = S*__expf(M - mg) + sg; M = mg; }
    else       { S += sg*__expf(mg - M); }
}

__global__ void k_col_lse(const float* __restrict__ Z){
    int b     = blockIdx.x >> 4;
    int chunk = blockIdx.x & 15;
    int cg    = threadIdx.x & 15;
    int rg    = threadIdx.x >> 4;
    __shared__ float rs[NNODE];
    for (int k=threadIdx.x; k<NNODE; k+=256) rs[k] = d_Rv[b*NNODE + k];
    __syncthreads();
    const float4* z = (const float4*)(Z + (size_t)b*NNODE*NNODE) + chunk*16 + cg;
    float4 m[4], s[4];
    #pragma unroll
    for (int j=0;j<4;j++){
        m[j] = make_float4(-3.4e38f,-3.4e38f,-3.4e38f,-3.4e38f);
        s[j] = make_float4(0.f,0.f,0.f,0.f);
    }
    int i0 = rg*64;
    for (int i=i0; i<i0+64; i+=8){
        float4 v[8]; float r[8];
        #pragma unroll
        for (int j=0;j<8;j++){ v[j] = z[(size_t)(i+j)*256]; r[j] = rs[i+j]; }
        #pragma unroll
        for (int j=0;j<8;j++){
            int st = j & 3;
            online_lse(v[j].x - r[j], m[st].x, s[st].x);
            online_lse(v[j].y - r[j], m[st].y, s[st].y);
            online_lse(v[j].z - r[j], m[st].z, s[st].z);
            online_lse(v[j].w - r[j], m[st].w, s[st].w);
        }
    }
    float4 M = m[0], S = s[0];
    #pragma unroll
    for (int j=1;j<4;j++){
        merge_lse(M.x, S.x, m[j].x, s[j].x);
        merge_lse(M.y, S.y, m[j].y, s[j].y);
        merge_lse(M.z, S.z, m[j].z, s[j].z);
        merge_lse(M.w, S.w, m[j].w, s[j].w);
    }
    __shared__ float4 sm16[16][16], ss16[16][16];
    sm16[rg][cg] = M; ss16[rg][cg] = S;
    __syncthreads();
    if (rg == 0){
        #pragma unroll
        for (int g=1; g<16; g++){
            float4 mg = sm16[g][cg], sg = ss16[g][cg];
            merge_lse(M.x, S.x, mg.x, sg.x);
            merge_lse(M.y, S.y, mg.y, sg.y);
            merge_lse(M.z, S.z, mg.z, sg.z);
            merge_lse(M.w, S.w, mg.w, sg.w);
        }
        int j = b*NNODE + chunk*64 + cg*4;
        d_Cv[j+0] = M.x + __logf(S.x);
        d_Cv[j+1] = M.y + __logf(S.y);
        d_Cv[j+2] = M.z + __logf(S.z);
        d_Cv[j+3] = M.w + __logf(S.w);
    }
}

__global__ void k_col_T(const float* __restrict__ Z){
    int b     = blockIdx.x >> 4;
    int chunk = blockIdx.x & 15;
    int cg    = threadIdx.x & 15;
    int rg    = threadIdx.x >> 4;
    __shared__ float rs[NNODE];
    for (int k=threadIdx.x; k<NNODE; k+=256) rs[k] = d_Rv[b*NNODE + k];
    __syncthreads();
    float4 cj = *((const float4*)(d_Cv + b*NNODE) + chunk*16 + cg);
    const float4* z = (const float4*)(Z + (size_t)b*NNODE*NNODE) + chunk*16 + cg;
    float4 s = {0.f,0.f,0.f,0.f};
    int i0 = rg*64;
    for (int i=i0; i<i0+64; i+=8){
        float4 v[8]; float r[8];
        #pragma unroll
        for (int j=0;j<8;j++){ v[j] = z[(size_t)(i+j)*256]; r[j] = rs[i+j]; }
        #pragma unroll
        for (int j=0;j<8;j++){
            s.x += __expf(v[j].x - r[j] - cj.x);
            s.y += __expf(v[j].y - r[j] - cj.y);
            s.z += __expf(v[j].z - r[j] - cj.z);
            s.w += __expf(v[j].w - r[j] - cj.w);
        }
    }
    __shared__ float4 ss16[16][16];
    ss16[rg][cg] = s;
    __syncthreads();
    if (rg == 0){
        #pragma unroll
        for (int g=1; g<16; g++){
            float4 sg = ss16[g][cg];
            s.x += sg.x; s.y += sg.y; s.z += sg.z; s.w += sg.w;
        }
        int j = b*NNODE + chunk*64 + cg*4;
        d_Tv[j+0]=s.x; d_Tv[j+1]=s.y; d_Tv[j+2]=s.z; d_Tv[j+3]=s.w;
    }
}

__global__ void k_final(const float* __restrict__ Z, float* __restrict__ P){
    size_t t = (size_t)blockIdx.x*256 + threadIdx.x;
    int row = (int)(t >> 10);
    int b   = row >> 10;
    int j   = (int)(t & 1023);
    P[t] = __expf(Z[t] - d_Rv[row] - d_Cv[b*NNODE + j]) / d_Tv[b*NNODE + j];
}

extern "C" void kernel_launch(void* const* d_in, const int* in_sizes, int n_in,
                              void* d_out, int out_size) {
    const float* X      = (const float*)d_in[0];
    const float* adj    = (const float*)d_in[1];
    const float* w_in   = (const float*)d_in[2];
    const float* b_in   = (const float*)d_in[3];
    const float* cw1    = (const float*)d_in[4];
    const float* cb1    = (const float*)d_in[5];
    const float* cw2    = (const float*)d_in[6];
    const float* cb2    = (const float*)d_in[7];
    const float* ca     = (const float*)d_in[8];
    const float* m1w    = (const float*)d_in[9];
    const float* m1b    = (const float*)d_in[10];
    const float* m2w    = (const float*)d_in[11];
    const float* m2b    = (const float*)d_in[12];
    float* Pout = (float*)d_out;
    float* Z0   = Pout + (size_t)TOTEL;

    float *hid, *hs, *g, *u1, *u2, *u3, *u4, *hp, *mid, *lg;
    cudaGetSymbolAddress((void**)&hid, d_hid);
    cudaGetSymbolAddress((void**)&hs,  d_hs);
    cudaGetSymbolAddress((void**)&g,   d_g);
    cudaGetSymbolAddress((void**)&u1,  d_u1);
    cudaGetSymbolAddress((void**)&u2,  d_u2);
    cudaGetSymbolAddress((void**)&u3,  d_u3);
    cudaGetSymbolAddress((void**)&u4,  d_u4);
    cudaGetSymbolAddress((void**)&hp,  d_hp);
    cudaGetSymbolAddress((void**)&mid, d_mid);
    cudaGetSymbolAddress((void**)&lg,  d_logits);
    float *dis, *invdeg;
    cudaGetSymbolAddress((void**)&dis,    d_dis);
    cudaGetSymbolAddress((void**)&invdeg, d_invdeg);

    k_adj_stats<<<NROWS/8, 256>>>(adj);

    // h0 = X @ w_in^T + b_in
    k_mma_nt<<<dim3(2,128), 256>>>(X, 128, w_in, 128, b_in, hid, 768, 0);

    dim3 tg(2, 8, 16);
    dim3 tgd(4, 8, 16);
    for (int l = 0; l < 2; l++){
        int off  = 256*l;
        int offn = 256*(l+1);
        k_scale_hs<<<NROWS*HD/256, 256>>>(off);
        k_mma_dual<<<tgd, 256>>>(adj, hs, g, dis, hid+off, 768, u1, invdeg);
        k_mma<<<tg, 256>>>(adj, u1, 256, u2, 2, u1, 256, invdeg);
        k_mma<<<tg, 256>>>(adj, u2, 256, u3, 2, u2, 256, invdeg);
        k_mma<<<tg, 256>>>(adj, u3, 256, u4, 2, u3, 256, invdeg);
        k_attn<<<NROWS, 256>>>(off, ca + l*512);
        k_mma_nt<<<dim3(2,128), 256>>>(hp,  256, cw1 + l*65536, 256, cb1 + l*256, mid, 256, 1);
        k_mma_nt<<<dim3(2,128), 256>>>(mid, 256, cw2 + l*65536, 256, cb2 + l*256, hid + offn, 768, 1);
    }

    // mlp1 + mlp2
    k_mma_nt<<<dim3(2,128), 256>>>(hid, 768, m1w, 768, m1b, mid, 256, 1);
    k_mma_nt<<<dim3(8,128), 256>>>(mid, 256, m2w, 256, m2b, lg, 1024, 2);

    // Z0 = (logits + gumbel)/tau  (gsinit output)
    k_z0<<<TOTEL/256, 256>>>(Z0);

    // Sinkhorn: rank-1 log-domain state (R, C)
    k_zeroC<<<NROWS/256, 256>>>();
    for (int it = 0; it < 20; it++){
        k_row_lse<<<NROWS/8, 256>>>(Z0);
        k_col_lse<<<256, 256>>>(Z0);
    }
    k_row_lse<<<NROWS/8, 256>>>(Z0);
    k_col_T  <<<256, 256>>>(Z0);
    k_final  <<<TOTEL/256, 256>>>(Z0, Pout);
}